// round 1
// baseline (speedup 1.0000x reference)
#include <cuda_runtime.h>
#include <math.h>

// Problem constants
#define BATCH 4
#define SEQ   4096
#define DIM   1024
#define MROWS (BATCH * SEQ)          // 16384

// Scan chunking
#define CHUNK_L 128
#define NCHUNK  (SEQ / CHUNK_L)      // 32

// GEMM tiling
#define BM 128
#define BN 128
#define BK 16
#define TM 8
#define TN 8
#define GEMM_THREADS 256

// ---------------------------------------------------------------------------
// Scratch (no cudaMalloc allowed)
// ---------------------------------------------------------------------------
__device__ float g_k[MROWS * DIM];       // 64 MB
__device__ float g_v[MROWS * DIM];       // 64 MB
__device__ float g_r[MROWS * DIM];       // 64 MB (pre-sigmoid r)
__device__ float g_wo_in[MROWS * DIM];   // 64 MB (r * wkv, input to final GEMM)
__device__ float g_chunk_sum[BATCH * NCHUNK * DIM];
__device__ float g_state_in[BATCH * NCHUNK * DIM];

// ---------------------------------------------------------------------------
// FP32 NT GEMM: C[m][n] = sum_k A[m*K+k] * B[n*K+k]
// M, N, K all multiples of tile sizes (16384 / 1024 / 1024) -> no bounds checks
// ---------------------------------------------------------------------------
__global__ __launch_bounds__(GEMM_THREADS, 2)
void gemm_nt_kernel(const float* __restrict__ A,
                    const float* __restrict__ B,
                    float* __restrict__ C,
                    int M, int N, int K)
{
    __shared__ float As[BK][BM];
    __shared__ float Bs[BK][BN];

    const int bm = blockIdx.y * BM;
    const int bn = blockIdx.x * BN;
    const int tid = threadIdx.x;
    const int tx = tid & 15;        // 0..15  -> N direction
    const int ty = tid >> 4;        // 0..15  -> M direction

    float acc[TM][TN];
#pragma unroll
    for (int i = 0; i < TM; i++)
#pragma unroll
        for (int j = 0; j < TN; j++)
            acc[i][j] = 0.0f;

    for (int k0 = 0; k0 < K; k0 += BK) {
        // Load 128x16 A tile and 128x16 B tile (each 512 float4, 2 per thread),
        // storing transposed into shared: As[k][m], Bs[k][n].
#pragma unroll
        for (int i = 0; i < 2; i++) {
            int lin = tid * 2 + i;          // 0..511
            int row = lin >> 2;             // 0..127
            int c4  = lin & 3;              // which float4 along K
            float4 a = *(const float4*)(A + (size_t)(bm + row) * K + k0 + c4 * 4);
            As[c4 * 4 + 0][row] = a.x;
            As[c4 * 4 + 1][row] = a.y;
            As[c4 * 4 + 2][row] = a.z;
            As[c4 * 4 + 3][row] = a.w;
            float4 b = *(const float4*)(B + (size_t)(bn + row) * K + k0 + c4 * 4);
            Bs[c4 * 4 + 0][row] = b.x;
            Bs[c4 * 4 + 1][row] = b.y;
            Bs[c4 * 4 + 2][row] = b.z;
            Bs[c4 * 4 + 3][row] = b.w;
        }
        __syncthreads();

#pragma unroll
        for (int kk = 0; kk < BK; kk++) {
            float a[TM], b[TN];
#pragma unroll
            for (int i = 0; i < TM; i++) a[i] = As[kk][ty * TM + i];
#pragma unroll
            for (int j = 0; j < TN; j++) b[j] = Bs[kk][tx * TN + j];
#pragma unroll
            for (int i = 0; i < TM; i++)
#pragma unroll
                for (int j = 0; j < TN; j++)
                    acc[i][j] = fmaf(a[i], b[j], acc[i][j]);
        }
        __syncthreads();
    }

#pragma unroll
    for (int i = 0; i < TM; i++) {
        float* crow = C + (size_t)(bm + ty * TM + i) * N + bn + tx * TN;
#pragma unroll
        for (int j = 0; j < TN; j += 4) {
            float4 val = make_float4(acc[i][j], acc[i][j + 1], acc[i][j + 2], acc[i][j + 3]);
            *(float4*)(crow + j) = val;
        }
    }
}

// ---------------------------------------------------------------------------
// Scan pass A: per-(batch, chunk, channel) local reduction with zero init.
// chunk_sum = sum_{t in chunk} decay^(L-1-t) * kv_t
// grid (NCHUNK, BATCH), block DIM threads
// ---------------------------------------------------------------------------
__global__ void scan_passA(const float* __restrict__ td)
{
    const int d = threadIdx.x;
    const int c = blockIdx.x;
    const int b = blockIdx.y;

    const float decay = expf(-expf(td[d]));

    const size_t base = ((size_t)b * SEQ + (size_t)c * CHUNK_L) * DIM + d;
    float s = 0.0f;
#pragma unroll 4
    for (int t = 0; t < CHUNK_L; t++) {
        float kv = g_k[base + (size_t)t * DIM] * g_v[base + (size_t)t * DIM];
        s = fmaf(decay, s, kv);
    }
    g_chunk_sum[((size_t)b * NCHUNK + c) * DIM + d] = s;
}

// ---------------------------------------------------------------------------
// Scan pass B: sequential carry across chunks. grid BATCH, block DIM.
// state_in[b][c] = state entering chunk c.
// ---------------------------------------------------------------------------
__global__ void scan_passB(const float* __restrict__ td)
{
    const int d = threadIdx.x;
    const int b = blockIdx.x;

    const float decayL = expf(-(float)CHUNK_L * expf(td[d]));

    float carry = 0.0f;
#pragma unroll
    for (int c = 0; c < NCHUNK; c++) {
        const size_t idx = ((size_t)b * NCHUNK + c) * DIM + d;
        g_state_in[idx] = carry;
        carry = fmaf(decayL, carry, g_chunk_sum[idx]);
    }
}

// ---------------------------------------------------------------------------
// Scan pass C: replay each chunk with correct incoming state; produce
// g_wo_in = sigmoid(r) * (state + eu*kv). grid (NCHUNK, BATCH), block DIM.
// ---------------------------------------------------------------------------
__global__ void scan_passC(const float* __restrict__ td,
                           const float* __restrict__ tf)
{
    const int d = threadIdx.x;
    const int c = blockIdx.x;
    const int b = blockIdx.y;

    const float decay = expf(-expf(td[d]));
    const float eu    = expf(tf[d]);

    float state = g_state_in[((size_t)b * NCHUNK + c) * DIM + d];

    const size_t base = ((size_t)b * SEQ + (size_t)c * CHUNK_L) * DIM + d;
#pragma unroll 4
    for (int t = 0; t < CHUNK_L; t++) {
        const size_t idx = base + (size_t)t * DIM;
        float kv  = g_k[idx] * g_v[idx];
        float wkv = fmaf(eu, kv, state);
        state = fmaf(decay, state, kv);
        float rp = g_r[idx];
        float rs = 1.0f / (1.0f + expf(-rp));
        g_wo_in[idx] = rs * wkv;
    }
}

// ---------------------------------------------------------------------------
// Launch
// ---------------------------------------------------------------------------
extern "C" void kernel_launch(void* const* d_in, const int* in_sizes, int n_in,
                              void* d_out, int out_size)
{
    const float* x  = (const float*)d_in[0];
    const float* Wk = (const float*)d_in[1];
    const float* Wv = (const float*)d_in[2];
    const float* Wr = (const float*)d_in[3];
    const float* Wo = (const float*)d_in[4];
    const float* td = (const float*)d_in[5];
    const float* tf = (const float*)d_in[6];
    float* out = (float*)d_out;

    float *k, *v, *r, *wo_in;
    cudaGetSymbolAddress((void**)&k,     g_k);
    cudaGetSymbolAddress((void**)&v,     g_v);
    cudaGetSymbolAddress((void**)&r,     g_r);
    cudaGetSymbolAddress((void**)&wo_in, g_wo_in);

    dim3 ggrid(DIM / BN, MROWS / BM);   // (8, 128)
    dim3 gblk(GEMM_THREADS);

    // Projections
    gemm_nt_kernel<<<ggrid, gblk>>>(x, Wk, k, MROWS, DIM, DIM);
    gemm_nt_kernel<<<ggrid, gblk>>>(x, Wv, v, MROWS, DIM, DIM);
    gemm_nt_kernel<<<ggrid, gblk>>>(x, Wr, r, MROWS, DIM, DIM);

    // Chunked linear scan
    dim3 sgrid(NCHUNK, BATCH);
    scan_passA<<<sgrid, DIM>>>(td);
    scan_passB<<<BATCH, DIM>>>(td);
    scan_passC<<<sgrid, DIM>>>(td, tf);

    // Output projection
    gemm_nt_kernel<<<ggrid, gblk>>>(wo_in, Wo, out, MROWS, DIM, DIM);
}

// round 4
// speedup vs baseline: 1.7782x; 1.7782x over previous
#include <cuda_runtime.h>
#include <cuda_bf16.h>
#include <cstdint>
#include <math.h>

// Problem constants
#define BATCH 4
#define SEQ   4096
#define DIM   1024
#define MROWS (BATCH * SEQ)          // 16384

// Scan chunking
#define CHUNK_L 128
#define NCHUNK  (SEQ / CHUNK_L)      // 32

// GEMM tiling
#define BM 128
#define BN 128
#define BK 32                         // bf16 K elems per stage (64B rows)
#define KCHUNKS (DIM / BK)            // 32
#define NSTAGE 3
#define GTHREADS 256

#define TILE_B  (128 * BK * 2)        // 8192 B per bf16 tile
#define STAGE_B (4 * TILE_B)          // Ahi, Alo, Bhi, Blo = 32768 B
#define SMEM_TOTAL (NSTAGE * STAGE_B) // 98304 B

// ---------------------------------------------------------------------------
// Scratch (no cudaMalloc allowed)
// ---------------------------------------------------------------------------
__device__ float g_k[MROWS * DIM];
__device__ float g_v[MROWS * DIM];
__device__ float g_r[MROWS * DIM];
__device__ float g_chunk_sum[BATCH * NCHUNK * DIM];
__device__ float g_state_in[BATCH * NCHUNK * DIM];

__device__ __nv_bfloat16 g_xhi[MROWS * DIM];
__device__ __nv_bfloat16 g_xlo[MROWS * DIM];
__device__ __nv_bfloat16 g_whi[4][DIM * DIM];
__device__ __nv_bfloat16 g_wlo[4][DIM * DIM];
__device__ __nv_bfloat16 g_ohi[MROWS * DIM];   // wo_in hi
__device__ __nv_bfloat16 g_olo[MROWS * DIM];   // wo_in lo

// ---------------------------------------------------------------------------
// Helpers
// ---------------------------------------------------------------------------
__device__ __forceinline__ uint32_t smem_u32(const void* p) {
    uint32_t a;
    asm("{ .reg .u64 t; cvta.to.shared.u64 t, %1; cvt.u32.u64 %0, t; }"
        : "=r"(a) : "l"(p));
    return a;
}

// Split a float4 into hi/lo bf16x2 pairs (packed: .x holds elems 0,1)
__device__ __forceinline__ void split4(float4 f, uint2& hi, uint2& lo) {
    uint32_t h01, h23;
    asm("cvt.rn.bf16x2.f32 %0, %2, %1;" : "=r"(h01) : "f"(f.x), "f"(f.y));
    asm("cvt.rn.bf16x2.f32 %0, %2, %1;" : "=r"(h23) : "f"(f.z), "f"(f.w));
    float hx = __uint_as_float(h01 << 16);
    float hy = __uint_as_float(h01 & 0xFFFF0000u);
    float hz = __uint_as_float(h23 << 16);
    float hw = __uint_as_float(h23 & 0xFFFF0000u);
    uint32_t l01, l23;
    asm("cvt.rn.bf16x2.f32 %0, %2, %1;" : "=r"(l01) : "f"(f.x - hx), "f"(f.y - hy));
    asm("cvt.rn.bf16x2.f32 %0, %2, %1;" : "=r"(l23) : "f"(f.z - hz), "f"(f.w - hw));
    hi = make_uint2(h01, h23);
    lo = make_uint2(l01, l23);
}

__device__ __forceinline__ void cp_async16(uint32_t dst, const void* src) {
    asm volatile("cp.async.cg.shared.global [%0], [%1], 16;"
                 :: "r"(dst), "l"(src) : "memory");
}
__device__ __forceinline__ void cp_commit() {
    asm volatile("cp.async.commit_group;" ::: "memory");
}
__device__ __forceinline__ void cp_wait1() {
    asm volatile("cp.async.wait_group 1;" ::: "memory");
}

__device__ __forceinline__ void ldmx4(uint32_t* r, uint32_t addr) {
    asm volatile("ldmatrix.sync.aligned.m8n8.x4.shared.b16 {%0,%1,%2,%3}, [%4];"
                 : "=r"(r[0]), "=r"(r[1]), "=r"(r[2]), "=r"(r[3]) : "r"(addr));
}

__device__ __forceinline__ void mma_bf16(float* d, const uint32_t* a,
                                         const uint32_t* b) {
    asm volatile(
        "mma.sync.aligned.m16n8k16.row.col.f32.bf16.bf16.f32 "
        "{%0,%1,%2,%3}, {%4,%5,%6,%7}, {%8,%9}, {%0,%1,%2,%3};"
        : "+f"(d[0]), "+f"(d[1]), "+f"(d[2]), "+f"(d[3])
        : "r"(a[0]), "r"(a[1]), "r"(a[2]), "r"(a[3]), "r"(b[0]), "r"(b[1]));
}

// SMEM swizzle for 64B rows (conflict-free ldmatrix)
__device__ __forceinline__ uint32_t sw_off(uint32_t r, uint32_t kb) {
    return r * 64 + (kb ^ (((r >> 1) & 3) << 4));
}

// ---------------------------------------------------------------------------
// Split fp32 -> hi/lo bf16 (elementwise, float4 granularity)
// ---------------------------------------------------------------------------
__global__ void convert_split(const float* __restrict__ src,
                              __nv_bfloat16* __restrict__ hi,
                              __nv_bfloat16* __restrict__ lo, int n4)
{
    for (int i = blockIdx.x * blockDim.x + threadIdx.x; i < n4;
         i += gridDim.x * blockDim.x) {
        float4 f = ((const float4*)src)[i];
        uint2 h, l;
        split4(f, h, l);
        ((uint2*)hi)[i] = h;
        ((uint2*)lo)[i] = l;
    }
}

// ---------------------------------------------------------------------------
// bf16x3 NT GEMM via mma.sync: C[m][n] = sum_k A[m][k]*B[n][k]
// A,B given as pre-split hi/lo bf16 arrays. grid (DIM/BN, MROWS/BM), 256 thr.
// ---------------------------------------------------------------------------
__global__ __launch_bounds__(GTHREADS, 1)
void gemm_bf16x3(const __nv_bfloat16* __restrict__ Ahi,
                 const __nv_bfloat16* __restrict__ Alo,
                 const __nv_bfloat16* __restrict__ Bhi,
                 const __nv_bfloat16* __restrict__ Blo,
                 float* __restrict__ C)
{
    extern __shared__ char smem[];
    const uint32_t sb = smem_u32(smem);
    const int tid = threadIdx.x;
    const int wid = tid >> 5;
    const int lane = tid & 31;
    const int bm = blockIdx.y * BM;
    const int bn = blockIdx.x * BN;

    const int warp_m = (wid >> 1) * 32;   // 0,32,64,96
    const int warp_n = (wid & 1) * 64;    // 0,64

    // cp.async load mapping: this thread handles 8 x 16B chunks per stage
    // (2 per tile). idx = i*256+tid in [0,512): r=idx>>2, kq=(idx&3)*16.
    const __nv_bfloat16* srcs[4] = {Ahi, Alo, Bhi, Blo};

    auto issue_stage = [&](int c, int s) {
        const uint32_t stage = sb + s * STAGE_B;
#pragma unroll
        for (int tile = 0; tile < 4; tile++) {
            const __nv_bfloat16* src = srcs[tile];
            const int rowbase = (tile < 2) ? bm : bn;
#pragma unroll
            for (int i = 0; i < 2; i++) {
                const int idx = i * 256 + tid;   // 0..511
                const uint32_t r = idx >> 2;
                const uint32_t kq = (idx & 3) * 16;
                const uint32_t dst = stage + tile * TILE_B + sw_off(r, kq);
                const char* sp = (const char*)(src + (size_t)(rowbase + r) * DIM
                                               + c * BK) + kq;
                cp_async16(dst, sp);
            }
        }
    };

    // Prologue: stages 0, 1
    issue_stage(0, 0); cp_commit();
    issue_stage(1, 1); cp_commit();

    float acc[2][8][4];
#pragma unroll
    for (int mt = 0; mt < 2; mt++)
#pragma unroll
        for (int nt = 0; nt < 8; nt++)
#pragma unroll
            for (int j = 0; j < 4; j++) acc[mt][nt][j] = 0.0f;

    // Precompute per-lane ldmatrix row/col indices
    const int gA = lane >> 3, rlA = lane & 7;
    // A: g0:+0,k0  g1:+8,k0  g2:+0,k16  g3:+8,k16
    const int a_row_off = (gA & 1) * 8 + rlA;
    const int a_kb_off = (gA >> 1) * 16;
    // B: g0:n+0,k0  g1:n+0,k16  g2:n+8,k0  g3:n+8,k16
    const int b_row_off = (gA >> 1) * 8 + rlA;
    const int b_kb_off = (gA & 1) * 16;

    for (int c = 0; c < KCHUNKS; c++) {
        cp_wait1();
        __syncthreads();
        if (c + 2 < KCHUNKS) issue_stage(c + 2, (c + 2) % NSTAGE);
        cp_commit();

        const uint32_t stage = sb + (c % NSTAGE) * STAGE_B;
        const uint32_t sAh = stage;
        const uint32_t sAl = stage + TILE_B;
        const uint32_t sBh = stage + 2 * TILE_B;
        const uint32_t sBl = stage + 3 * TILE_B;

#pragma unroll
        for (int ks = 0; ks < 2; ks++) {
            const uint32_t kbase = ks * 32;
            uint32_t ah[2][4], al[2][4];
#pragma unroll
            for (int mt = 0; mt < 2; mt++) {
                const uint32_t r = warp_m + mt * 16 + a_row_off;
                const uint32_t kb = kbase + a_kb_off;
                ldmx4(ah[mt], sAh + sw_off(r, kb));
                ldmx4(al[mt], sAl + sw_off(r, kb));
            }
            uint32_t bh[8][2], bl[8][2];
#pragma unroll
            for (int p = 0; p < 4; p++) {
                const uint32_t n = warp_n + p * 16 + b_row_off;
                const uint32_t kb = kbase + b_kb_off;
                uint32_t t[4];
                ldmx4(t, sBh + sw_off(n, kb));
                bh[2 * p][0] = t[0]; bh[2 * p][1] = t[1];
                bh[2 * p + 1][0] = t[2]; bh[2 * p + 1][1] = t[3];
                ldmx4(t, sBl + sw_off(n, kb));
                bl[2 * p][0] = t[0]; bl[2 * p][1] = t[1];
                bl[2 * p + 1][0] = t[2]; bl[2 * p + 1][1] = t[3];
            }
#pragma unroll
            for (int mt = 0; mt < 2; mt++)
#pragma unroll
                for (int nt = 0; nt < 8; nt++) {
                    mma_bf16(acc[mt][nt], ah[mt], bh[nt]);
                    mma_bf16(acc[mt][nt], ah[mt], bl[nt]);
                    mma_bf16(acc[mt][nt], al[mt], bh[nt]);
                }
        }
        __syncthreads();
    }

    // Epilogue: accum -> C
    const int er = lane >> 2;          // 0..7
    const int ec = (lane & 3) * 2;     // 0,2,4,6
#pragma unroll
    for (int mt = 0; mt < 2; mt++) {
        const int row0 = bm + warp_m + mt * 16 + er;
#pragma unroll
        for (int nt = 0; nt < 8; nt++) {
            const int col = bn + warp_n + nt * 8 + ec;
            *(float2*)(C + (size_t)row0 * DIM + col) =
                make_float2(acc[mt][nt][0], acc[mt][nt][1]);
            *(float2*)(C + (size_t)(row0 + 8) * DIM + col) =
                make_float2(acc[mt][nt][2], acc[mt][nt][3]);
        }
    }
}

// ---------------------------------------------------------------------------
// Scan pass A: per-(batch, chunk, channel) local reduction with zero init.
// ---------------------------------------------------------------------------
__global__ void scan_passA(const float* __restrict__ td)
{
    const int d = threadIdx.x;
    const int c = blockIdx.x;
    const int b = blockIdx.y;

    const float decay = expf(-expf(td[d]));

    const size_t base = ((size_t)b * SEQ + (size_t)c * CHUNK_L) * DIM + d;
    float s = 0.0f;
#pragma unroll 4
    for (int t = 0; t < CHUNK_L; t++) {
        float kv = g_k[base + (size_t)t * DIM] * g_v[base + (size_t)t * DIM];
        s = fmaf(decay, s, kv);
    }
    g_chunk_sum[((size_t)b * NCHUNK + c) * DIM + d] = s;
}

// ---------------------------------------------------------------------------
// Scan pass B: sequential carry across chunks.
// ---------------------------------------------------------------------------
__global__ void scan_passB(const float* __restrict__ td)
{
    const int d = threadIdx.x;
    const int b = blockIdx.x;

    const float decayL = expf(-(float)CHUNK_L * expf(td[d]));

    float carry = 0.0f;
#pragma unroll
    for (int c = 0; c < NCHUNK; c++) {
        const size_t idx = ((size_t)b * NCHUNK + c) * DIM + d;
        g_state_in[idx] = carry;
        carry = fmaf(decayL, carry, g_chunk_sum[idx]);
    }
}

// ---------------------------------------------------------------------------
// Scan pass C: replay with correct incoming state; writes hi/lo bf16 split of
// sigmoid(r)*wkv directly (input to the final GEMM).
// ---------------------------------------------------------------------------
__global__ void scan_passC(const float* __restrict__ td,
                           const float* __restrict__ tf)
{
    const int d = threadIdx.x;
    const int c = blockIdx.x;
    const int b = blockIdx.y;

    const float decay = expf(-expf(td[d]));
    const float eu    = expf(tf[d]);

    float state = g_state_in[((size_t)b * NCHUNK + c) * DIM + d];

    const size_t base = ((size_t)b * SEQ + (size_t)c * CHUNK_L) * DIM + d;
#pragma unroll 4
    for (int t = 0; t < CHUNK_L; t++) {
        const size_t idx = base + (size_t)t * DIM;
        float kv  = g_k[idx] * g_v[idx];
        float wkv = fmaf(eu, kv, state);
        state = fmaf(decay, state, kv);
        float rp = g_r[idx];
        float rs = 1.0f / (1.0f + expf(-rp));
        float o = rs * wkv;
        __nv_bfloat16 h = __float2bfloat16(o);
        __nv_bfloat16 l = __float2bfloat16(o - __bfloat162float(h));
        g_ohi[idx] = h;
        g_olo[idx] = l;
    }
}

// ---------------------------------------------------------------------------
// Launch
// ---------------------------------------------------------------------------
extern "C" void kernel_launch(void* const* d_in, const int* in_sizes, int n_in,
                              void* d_out, int out_size)
{
    const float* x  = (const float*)d_in[0];
    const float* Wk = (const float*)d_in[1];
    const float* Wv = (const float*)d_in[2];
    const float* Wr = (const float*)d_in[3];
    const float* Wo = (const float*)d_in[4];
    const float* td = (const float*)d_in[5];
    const float* tf = (const float*)d_in[6];
    float* out = (float*)d_out;

    float *k, *v, *r;
    cudaGetSymbolAddress((void**)&k, g_k);
    cudaGetSymbolAddress((void**)&v, g_v);
    cudaGetSymbolAddress((void**)&r, g_r);
    __nv_bfloat16 *xhi, *xlo, *whi, *wlo, *ohi, *olo;
    cudaGetSymbolAddress((void**)&xhi, g_xhi);
    cudaGetSymbolAddress((void**)&xlo, g_xlo);
    cudaGetSymbolAddress((void**)&whi, g_whi);
    cudaGetSymbolAddress((void**)&wlo, g_wlo);
    cudaGetSymbolAddress((void**)&ohi, g_ohi);
    cudaGetSymbolAddress((void**)&olo, g_olo);

    cudaFuncSetAttribute(gemm_bf16x3, cudaFuncAttributeMaxDynamicSharedMemorySize,
                         SMEM_TOTAL);

    // Pre-split inputs to hi/lo bf16
    convert_split<<<4096, 256>>>(x, xhi, xlo, MROWS * DIM / 4);
    const float* Ws[4] = {Wk, Wv, Wr, Wo};
    for (int i = 0; i < 4; i++)
        convert_split<<<1024, 256>>>(Ws[i], whi + (size_t)i * DIM * DIM,
                                     wlo + (size_t)i * DIM * DIM, DIM * DIM / 4);

    dim3 ggrid(DIM / BN, MROWS / BM);   // (8, 128)

    // Projections
    gemm_bf16x3<<<ggrid, GTHREADS, SMEM_TOTAL>>>(xhi, xlo,
        whi + 0 * (size_t)DIM * DIM, wlo + 0 * (size_t)DIM * DIM, k);
    gemm_bf16x3<<<ggrid, GTHREADS, SMEM_TOTAL>>>(xhi, xlo,
        whi + 1 * (size_t)DIM * DIM, wlo + 1 * (size_t)DIM * DIM, v);
    gemm_bf16x3<<<ggrid, GTHREADS, SMEM_TOTAL>>>(xhi, xlo,
        whi + 2 * (size_t)DIM * DIM, wlo + 2 * (size_t)DIM * DIM, r);

    // Chunked linear scan
    dim3 sgrid(NCHUNK, BATCH);
    scan_passA<<<sgrid, DIM>>>(td);
    scan_passB<<<BATCH, DIM>>>(td);
    scan_passC<<<sgrid, DIM>>>(td, tf);

    // Output projection
    gemm_bf16x3<<<ggrid, GTHREADS, SMEM_TOTAL>>>(ohi, olo,
        whi + 3 * (size_t)DIM * DIM, wlo + 3 * (size_t)DIM * DIM, out);
}

// round 6
// speedup vs baseline: 2.8999x; 1.6308x over previous
#include <cuda_runtime.h>
#include <cuda_fp16.h>
#include <cuda_bf16.h>
#include <cstdint>
#include <math.h>

// Problem constants
#define BATCH 4
#define SEQ   4096
#define DIM   1024
#define MROWS (BATCH * SEQ)          // 16384
#define NKVR  (3 * DIM)              // 3072 fused output channels

// Scan chunking
#define CHUNK_L 128
#define NCHUNK  (SEQ / CHUNK_L)      // 32

// GEMM tiling
#define BM 128
#define BN 128
#define BK 32                         // fp16 K elems per stage (64B rows)
#define KCHUNKS (DIM / BK)            // 32
#define NSTAGE 3
#define GTHREADS 256

#define TILE_B  (128 * BK * 2)        // 8192 B per fp16 tile
#define STAGE_B (3 * TILE_B)          // Ahi, Alo, Bh = 24576 B
#define SMEM_TOTAL (NSTAGE * STAGE_B) // 73728 B

// ---------------------------------------------------------------------------
// Scratch (no cudaMalloc allowed)
// ---------------------------------------------------------------------------
__device__ float g_kvr[MROWS * NKVR];            // fused k|v|r outputs (192 MB)
__device__ float g_chunk_sum[BATCH * NCHUNK * DIM];
__device__ float g_state_in[BATCH * NCHUNK * DIM];

__device__ __half g_xhi[MROWS * DIM];
__device__ __half g_xlo[MROWS * DIM];
__device__ __half g_wh[4 * DIM * DIM];           // Wk|Wv|Wr|Wo fp16 (concat rows)
__device__ __half g_ohi[MROWS * DIM];            // wo_in hi
__device__ __half g_olo[MROWS * DIM];            // wo_in lo

// ---------------------------------------------------------------------------
// Helpers
// ---------------------------------------------------------------------------
__device__ __forceinline__ uint32_t smem_u32(const void* p) {
    uint32_t a;
    asm("{ .reg .u64 t; cvta.to.shared.u64 t, %1; cvt.u32.u64 %0, t; }"
        : "=r"(a) : "l"(p));
    return a;
}

// Split float4 into fp16 hi/lo pairs (elem order: .x holds elems 0,1)
__device__ __forceinline__ void split4h(float4 f, uint2& hi, uint2& lo) {
    __half h0 = __float2half_rn(f.x), h1 = __float2half_rn(f.y);
    __half h2 = __float2half_rn(f.z), h3 = __float2half_rn(f.w);
    __half l0 = __float2half_rn(f.x - __half2float(h0));
    __half l1 = __float2half_rn(f.y - __half2float(h1));
    __half l2 = __float2half_rn(f.z - __half2float(h2));
    __half l3 = __float2half_rn(f.w - __half2float(h3));
    __half2 hp0 = __halves2half2(h0, h1), hp1 = __halves2half2(h2, h3);
    __half2 lp0 = __halves2half2(l0, l1), lp1 = __halves2half2(l2, l3);
    hi = make_uint2(*(uint32_t*)&hp0, *(uint32_t*)&hp1);
    lo = make_uint2(*(uint32_t*)&lp0, *(uint32_t*)&lp1);
}

__device__ __forceinline__ void cp_async16(uint32_t dst, const void* src) {
    asm volatile("cp.async.cg.shared.global [%0], [%1], 16;"
                 :: "r"(dst), "l"(src) : "memory");
}
__device__ __forceinline__ void cp_commit() {
    asm volatile("cp.async.commit_group;" ::: "memory");
}
__device__ __forceinline__ void cp_wait1() {
    asm volatile("cp.async.wait_group 1;" ::: "memory");
}

__device__ __forceinline__ void ldmx4(uint32_t* r, uint32_t addr) {
    asm volatile("ldmatrix.sync.aligned.m8n8.x4.shared.b16 {%0,%1,%2,%3}, [%4];"
                 : "=r"(r[0]), "=r"(r[1]), "=r"(r[2]), "=r"(r[3]) : "r"(addr));
}

__device__ __forceinline__ void mma_f16(float* d, const uint32_t* a,
                                        const uint32_t* b) {
    asm volatile(
        "mma.sync.aligned.m16n8k16.row.col.f32.f16.f16.f32 "
        "{%0,%1,%2,%3}, {%4,%5,%6,%7}, {%8,%9}, {%0,%1,%2,%3};"
        : "+f"(d[0]), "+f"(d[1]), "+f"(d[2]), "+f"(d[3])
        : "r"(a[0]), "r"(a[1]), "r"(a[2]), "r"(a[3]), "r"(b[0]), "r"(b[1]));
}

// SMEM swizzle for 64B rows (conflict-free ldmatrix)
__device__ __forceinline__ uint32_t sw_off(uint32_t r, uint32_t kb) {
    return r * 64 + (kb ^ (((r >> 1) & 3) << 4));
}

// ---------------------------------------------------------------------------
// Converts
// ---------------------------------------------------------------------------
__global__ void convert_hl(const float* __restrict__ src,
                           __half* __restrict__ hi,
                           __half* __restrict__ lo, int n4)
{
    for (int i = blockIdx.x * blockDim.x + threadIdx.x; i < n4;
         i += gridDim.x * blockDim.x) {
        float4 f = ((const float4*)src)[i];
        uint2 h, l;
        split4h(f, h, l);
        ((uint2*)hi)[i] = h;
        ((uint2*)lo)[i] = l;
    }
}

__global__ void convert_h(const float* __restrict__ src,
                          __half* __restrict__ dst, int n4)
{
    for (int i = blockIdx.x * blockDim.x + threadIdx.x; i < n4;
         i += gridDim.x * blockDim.x) {
        float4 f = ((const float4*)src)[i];
        __half2 p0 = __floats2half2_rn(f.x, f.y);
        __half2 p1 = __floats2half2_rn(f.z, f.w);
        ((uint2*)dst)[i] = make_uint2(*(uint32_t*)&p0, *(uint32_t*)&p1);
    }
}

// ---------------------------------------------------------------------------
// fp16x2 NT GEMM via mma.sync: C[m][n] = sum_k (Ahi+Alo)[m][k] * Bh[n][k]
// A row stride DIM, B row stride DIM, C row stride ldc.
// grid (N/BN, MROWS/BM), 256 threads.
// ---------------------------------------------------------------------------
__global__ __launch_bounds__(GTHREADS, 2)
void gemm_fp16x2(const __half* __restrict__ Ahi,
                 const __half* __restrict__ Alo,
                 const __half* __restrict__ Bh,
                 float* __restrict__ C, int ldc)
{
    extern __shared__ char smem[];
    const uint32_t sb = smem_u32(smem);
    const int tid = threadIdx.x;
    const int wid = tid >> 5;
    const int lane = tid & 31;
    const int bm = blockIdx.y * BM;
    const int bn = blockIdx.x * BN;

    const int warp_m = (wid >> 1) * 32;   // 0,32,64,96
    const int warp_n = (wid & 1) * 64;    // 0,64

    const __half* srcs[3] = {Ahi, Alo, Bh};

    auto issue_stage = [&](int c, int s) {
        const uint32_t stage = sb + s * STAGE_B;
#pragma unroll
        for (int tile = 0; tile < 3; tile++) {
            const __half* src = srcs[tile];
            const int rowbase = (tile < 2) ? bm : bn;
#pragma unroll
            for (int i = 0; i < 2; i++) {
                const int idx = i * 256 + tid;   // 0..511
                const uint32_t r = idx >> 2;
                const uint32_t kq = (idx & 3) * 16;
                const uint32_t dst = stage + tile * TILE_B + sw_off(r, kq);
                const char* sp = (const char*)(src + (size_t)(rowbase + r) * DIM
                                               + c * BK) + kq;
                cp_async16(dst, sp);
            }
        }
    };

    issue_stage(0, 0); cp_commit();
    issue_stage(1, 1); cp_commit();

    float acc[2][8][4];
#pragma unroll
    for (int mt = 0; mt < 2; mt++)
#pragma unroll
        for (int nt = 0; nt < 8; nt++)
#pragma unroll
            for (int j = 0; j < 4; j++) acc[mt][nt][j] = 0.0f;

    const int gA = lane >> 3, rlA = lane & 7;
    const int a_row_off = (gA & 1) * 8 + rlA;
    const int a_kb_off = (gA >> 1) * 16;
    const int b_row_off = (gA >> 1) * 8 + rlA;
    const int b_kb_off = (gA & 1) * 16;

    for (int c = 0; c < KCHUNKS; c++) {
        cp_wait1();
        __syncthreads();
        if (c + 2 < KCHUNKS) issue_stage(c + 2, (c + 2) % NSTAGE);
        cp_commit();

        const uint32_t stage = sb + (c % NSTAGE) * STAGE_B;
        const uint32_t sAh = stage;
        const uint32_t sAl = stage + TILE_B;
        const uint32_t sBh = stage + 2 * TILE_B;

#pragma unroll
        for (int ks = 0; ks < 2; ks++) {
            const uint32_t kbase = ks * 32;
            uint32_t ah[2][4], al[2][4];
#pragma unroll
            for (int mt = 0; mt < 2; mt++) {
                const uint32_t r = warp_m + mt * 16 + a_row_off;
                const uint32_t kb = kbase + a_kb_off;
                ldmx4(ah[mt], sAh + sw_off(r, kb));
                ldmx4(al[mt], sAl + sw_off(r, kb));
            }
            uint32_t bh[8][2];
#pragma unroll
            for (int p = 0; p < 4; p++) {
                const uint32_t n = warp_n + p * 16 + b_row_off;
                const uint32_t kb = kbase + b_kb_off;
                uint32_t t[4];
                ldmx4(t, sBh + sw_off(n, kb));
                bh[2 * p][0] = t[0]; bh[2 * p][1] = t[1];
                bh[2 * p + 1][0] = t[2]; bh[2 * p + 1][1] = t[3];
            }
#pragma unroll
            for (int mt = 0; mt < 2; mt++)
#pragma unroll
                for (int nt = 0; nt < 8; nt++) {
                    mma_f16(acc[mt][nt], ah[mt], bh[nt]);
                    mma_f16(acc[mt][nt], al[mt], bh[nt]);
                }
        }
        __syncthreads();
    }

    const int er = lane >> 2;
    const int ec = (lane & 3) * 2;
#pragma unroll
    for (int mt = 0; mt < 2; mt++) {
        const int row0 = bm + warp_m + mt * 16 + er;
#pragma unroll
        for (int nt = 0; nt < 8; nt++) {
            const int col = bn + warp_n + nt * 8 + ec;
            *(float2*)(C + (size_t)row0 * ldc + col) =
                make_float2(acc[mt][nt][0], acc[mt][nt][1]);
            *(float2*)(C + (size_t)(row0 + 8) * ldc + col) =
                make_float2(acc[mt][nt][2], acc[mt][nt][3]);
        }
    }
}

// ---------------------------------------------------------------------------
// Scan pass A: per-(batch, chunk, channel) local reduction with zero init.
// k at g_kvr[m*NKVR + d], v at g_kvr[m*NKVR + DIM + d].
// ---------------------------------------------------------------------------
__global__ void scan_passA(const float* __restrict__ td)
{
    const int d = threadIdx.x;
    const int c = blockIdx.x;
    const int b = blockIdx.y;

    const float decay = expf(-expf(td[d]));

    const size_t base = ((size_t)b * SEQ + (size_t)c * CHUNK_L) * NKVR + d;
    float s = 0.0f;
#pragma unroll 4
    for (int t = 0; t < CHUNK_L; t++) {
        const size_t idx = base + (size_t)t * NKVR;
        float kv = g_kvr[idx] * g_kvr[idx + DIM];
        s = fmaf(decay, s, kv);
    }
    g_chunk_sum[((size_t)b * NCHUNK + c) * DIM + d] = s;
}

// ---------------------------------------------------------------------------
// Scan pass B: sequential carry across chunks.
// ---------------------------------------------------------------------------
__global__ void scan_passB(const float* __restrict__ td)
{
    const int d = threadIdx.x;
    const int b = blockIdx.x;

    const float decayL = expf(-(float)CHUNK_L * expf(td[d]));

    float carry = 0.0f;
#pragma unroll
    for (int c = 0; c < NCHUNK; c++) {
        const size_t idx = ((size_t)b * NCHUNK + c) * DIM + d;
        g_state_in[idx] = carry;
        carry = fmaf(decayL, carry, g_chunk_sum[idx]);
    }
}

// ---------------------------------------------------------------------------
// Scan pass C: replay with correct incoming state; writes hi/lo fp16 split of
// sigmoid(r)*wkv (input to the final GEMM).
// ---------------------------------------------------------------------------
__global__ void scan_passC(const float* __restrict__ td,
                           const float* __restrict__ tf)
{
    const int d = threadIdx.x;
    const int c = blockIdx.x;
    const int b = blockIdx.y;

    const float decay = expf(-expf(td[d]));
    const float eu    = expf(tf[d]);

    float state = g_state_in[((size_t)b * NCHUNK + c) * DIM + d];

    const size_t rowbase = (size_t)b * SEQ + (size_t)c * CHUNK_L;
#pragma unroll 4
    for (int t = 0; t < CHUNK_L; t++) {
        const size_t row = rowbase + t;
        const size_t src = row * NKVR + d;
        float kv  = g_kvr[src] * g_kvr[src + DIM];
        float wkv = fmaf(eu, kv, state);
        state = fmaf(decay, state, kv);
        float rp = g_kvr[src + 2 * DIM];
        float rs = 1.0f / (1.0f + expf(-rp));
        float o = rs * wkv;
        __half h = __float2half_rn(o);
        __half l = __float2half_rn(o - __half2float(h));
        const size_t dst = row * DIM + d;
        g_ohi[dst] = h;
        g_olo[dst] = l;
    }
}

// ---------------------------------------------------------------------------
// Launch
// ---------------------------------------------------------------------------
extern "C" void kernel_launch(void* const* d_in, const int* in_sizes, int n_in,
                              void* d_out, int out_size)
{
    const float* x  = (const float*)d_in[0];
    const float* Wk = (const float*)d_in[1];
    const float* Wv = (const float*)d_in[2];
    const float* Wr = (const float*)d_in[3];
    const float* Wo = (const float*)d_in[4];
    const float* td = (const float*)d_in[5];
    const float* tf = (const float*)d_in[6];
    float* out = (float*)d_out;

    float* kvr;
    cudaGetSymbolAddress((void**)&kvr, g_kvr);
    __half *xhi, *xlo, *wh, *ohi, *olo;
    cudaGetSymbolAddress((void**)&xhi, g_xhi);
    cudaGetSymbolAddress((void**)&xlo, g_xlo);
    cudaGetSymbolAddress((void**)&wh,  g_wh);
    cudaGetSymbolAddress((void**)&ohi, g_ohi);
    cudaGetSymbolAddress((void**)&olo, g_olo);

    cudaFuncSetAttribute(gemm_fp16x2, cudaFuncAttributeMaxDynamicSharedMemorySize,
                         SMEM_TOTAL);

    // Pre-split activations, convert weights (Wk|Wv|Wr|Wo concatenated rows)
    convert_hl<<<4096, 256>>>(x, xhi, xlo, MROWS * DIM / 4);
    const float* Ws[4] = {Wk, Wv, Wr, Wo};
    for (int i = 0; i < 4; i++)
        convert_h<<<1024, 256>>>(Ws[i], wh + (size_t)i * DIM * DIM, DIM * DIM / 4);

    // Fused k|v|r projection: one GEMM, N = 3072
    dim3 ggrid_kvr(NKVR / BN, MROWS / BM);   // (24, 128)
    gemm_fp16x2<<<ggrid_kvr, GTHREADS, SMEM_TOTAL>>>(xhi, xlo, wh, kvr, NKVR);

    // Chunked linear scan
    dim3 sgrid(NCHUNK, BATCH);
    scan_passA<<<sgrid, DIM>>>(td);
    scan_passB<<<BATCH, DIM>>>(td);
    scan_passC<<<sgrid, DIM>>>(td, tf);

    // Output projection
    dim3 ggrid_o(DIM / BN, MROWS / BM);      // (8, 128)
    gemm_fp16x2<<<ggrid_o, GTHREADS, SMEM_TOTAL>>>(ohi, olo,
        wh + 3 * (size_t)DIM * DIM, out, DIM);
}

// round 9
// speedup vs baseline: 5.6840x; 1.9601x over previous
#include <cuda_runtime.h>
#include <cuda_fp16.h>
#include <cstdint>
#include <math.h>

// Problem constants
#define BATCH 4
#define SEQ   4096
#define DIM   1024
#define MROWS (BATCH * SEQ)          // 16384
#define NKVR  (3 * DIM)              // 3072 fused output channels

// Scan chunking
#define CHUNK_L 128
#define NCHUNK  (SEQ / CHUNK_L)      // 32

// GEMM tiling
#define BM 128
#define BN 128
#define BK 32                         // fp16 K elems per stage (64B rows)
#define KCHUNKS (DIM / BK)            // 32
#define NSTAGE 3
#define GTHREADS 256

#define TILE_B  (128 * BK * 2)        // 8192 B per fp16 tile

// ---------------------------------------------------------------------------
// Scratch (no cudaMalloc allowed)
// ---------------------------------------------------------------------------
__device__ float g_kvr[MROWS * NKVR];            // fused k|v|r outputs
__device__ float g_chunk_sum[BATCH * NCHUNK * DIM];
__device__ float g_state_in[BATCH * NCHUNK * DIM];

__device__ __half g_xhi[MROWS * DIM];
__device__ __half g_wh[4 * DIM * DIM];           // Wk|Wv|Wr|Wo fp16
__device__ __half g_ohi[MROWS * DIM];            // wo_in hi
__device__ __half g_olo[MROWS * DIM];            // wo_in lo

// ---------------------------------------------------------------------------
// Helpers
// ---------------------------------------------------------------------------
__device__ __forceinline__ uint32_t smem_u32(const void* p) {
    uint32_t a;
    asm("{ .reg .u64 t; cvta.to.shared.u64 t, %1; cvt.u32.u64 %0, t; }"
        : "=r"(a) : "l"(p));
    return a;
}

__device__ __forceinline__ void cp_async16(uint32_t dst, const void* src) {
    asm volatile("cp.async.cg.shared.global [%0], [%1], 16;"
                 :: "r"(dst), "l"(src) : "memory");
}
__device__ __forceinline__ void cp_commit() {
    asm volatile("cp.async.commit_group;" ::: "memory");
}
__device__ __forceinline__ void cp_wait1() {
    asm volatile("cp.async.wait_group 1;" ::: "memory");
}

__device__ __forceinline__ void ldmx4(uint32_t* r, uint32_t addr) {
    asm volatile("ldmatrix.sync.aligned.m8n8.x4.shared.b16 {%0,%1,%2,%3}, [%4];"
                 : "=r"(r[0]), "=r"(r[1]), "=r"(r[2]), "=r"(r[3]) : "r"(addr));
}

__device__ __forceinline__ void mma_f16(float* d, const uint32_t* a,
                                        const uint32_t* b) {
    asm volatile(
        "mma.sync.aligned.m16n8k16.row.col.f32.f16.f16.f32 "
        "{%0,%1,%2,%3}, {%4,%5,%6,%7}, {%8,%9}, {%0,%1,%2,%3};"
        : "+f"(d[0]), "+f"(d[1]), "+f"(d[2]), "+f"(d[3])
        : "r"(a[0]), "r"(a[1]), "r"(a[2]), "r"(a[3]), "r"(b[0]), "r"(b[1]));
}

// SMEM swizzle for 64B rows (conflict-free ldmatrix)
__device__ __forceinline__ uint32_t sw_off(uint32_t r, uint32_t kb) {
    return r * 64 + (kb ^ (((r >> 1) & 3) << 4));
}

// ---------------------------------------------------------------------------
// Converts
// ---------------------------------------------------------------------------
__global__ void convert_h(const float* __restrict__ src,
                          __half* __restrict__ dst, int n4)
{
    for (int i = blockIdx.x * blockDim.x + threadIdx.x; i < n4;
         i += gridDim.x * blockDim.x) {
        float4 f = ((const float4*)src)[i];
        __half2 p0 = __floats2half2_rn(f.x, f.y);
        __half2 p1 = __floats2half2_rn(f.z, f.w);
        ((uint2*)dst)[i] = make_uint2(*(uint32_t*)&p0, *(uint32_t*)&p1);
    }
}

// ---------------------------------------------------------------------------
// fp16 NT GEMM via mma.sync, NA A-terms: C[m][n] = sum_k (sum_t At)[m][k]*B[n][k]
// grid (N/BN, MROWS/BM), 256 threads.
// ---------------------------------------------------------------------------
template <int NA>
__global__ __launch_bounds__(GTHREADS, 2)
void gemm_fp16t(const __half* __restrict__ A0,
                const __half* __restrict__ A1,
                const __half* __restrict__ Bh,
                float* __restrict__ C, int ldc)
{
    constexpr int NTILES = NA + 1;
    constexpr int STAGE_B = NTILES * TILE_B;

    extern __shared__ char smem[];
    const uint32_t sb = smem_u32(smem);
    const int tid = threadIdx.x;
    const int wid = tid >> 5;
    const int lane = tid & 31;
    const int bm = blockIdx.y * BM;
    const int bn = blockIdx.x * BN;

    const int warp_m = (wid >> 1) * 32;   // 0,32,64,96
    const int warp_n = (wid & 1) * 64;    // 0,64

    const __half* srcs[NTILES];
    srcs[0] = A0;
    if (NA == 2) { srcs[1] = A1; srcs[NA] = Bh; }
    else         { srcs[NA] = Bh; }

    auto issue_stage = [&](int c, int s) {
        const uint32_t stage = sb + s * STAGE_B;
#pragma unroll
        for (int tile = 0; tile < NTILES; tile++) {
            const __half* src = srcs[tile];
            const int rowbase = (tile < NA) ? bm : bn;
#pragma unroll
            for (int i = 0; i < 2; i++) {
                const int idx = i * 256 + tid;   // 0..511
                const uint32_t r = idx >> 2;
                const uint32_t kq = (idx & 3) * 16;
                const uint32_t dst = stage + tile * TILE_B + sw_off(r, kq);
                const char* sp = (const char*)(src + (size_t)(rowbase + r) * DIM
                                               + c * BK) + kq;
                cp_async16(dst, sp);
            }
        }
    };

    issue_stage(0, 0); cp_commit();
    issue_stage(1, 1); cp_commit();

    float acc[2][8][4];
#pragma unroll
    for (int mt = 0; mt < 2; mt++)
#pragma unroll
        for (int nt = 0; nt < 8; nt++)
#pragma unroll
            for (int j = 0; j < 4; j++) acc[mt][nt][j] = 0.0f;

    const int gA = lane >> 3, rlA = lane & 7;
    const int a_row_off = (gA & 1) * 8 + rlA;
    const int a_kb_off = (gA >> 1) * 16;
    const int b_row_off = (gA >> 1) * 8 + rlA;
    const int b_kb_off = (gA & 1) * 16;

    for (int c = 0; c < KCHUNKS; c++) {
        cp_wait1();
        __syncthreads();
        if (c + 2 < KCHUNKS) issue_stage(c + 2, (c + 2) % NSTAGE);
        cp_commit();

        const uint32_t stage = sb + (c % NSTAGE) * STAGE_B;
        const uint32_t sB = stage + NA * TILE_B;

#pragma unroll
        for (int ks = 0; ks < 2; ks++) {
            const uint32_t kbase = ks * 32;
            uint32_t a[NA][2][4];
#pragma unroll
            for (int t = 0; t < NA; t++)
#pragma unroll
                for (int mt = 0; mt < 2; mt++) {
                    const uint32_t r = warp_m + mt * 16 + a_row_off;
                    const uint32_t kb = kbase + a_kb_off;
                    ldmx4(a[t][mt], stage + t * TILE_B + sw_off(r, kb));
                }
            uint32_t bh[8][2];
#pragma unroll
            for (int p = 0; p < 4; p++) {
                const uint32_t n = warp_n + p * 16 + b_row_off;
                const uint32_t kb = kbase + b_kb_off;
                uint32_t t4[4];
                ldmx4(t4, sB + sw_off(n, kb));
                bh[2 * p][0] = t4[0]; bh[2 * p][1] = t4[1];
                bh[2 * p + 1][0] = t4[2]; bh[2 * p + 1][1] = t4[3];
            }
#pragma unroll
            for (int mt = 0; mt < 2; mt++)
#pragma unroll
                for (int nt = 0; nt < 8; nt++)
#pragma unroll
                    for (int t = 0; t < NA; t++)
                        mma_f16(acc[mt][nt], a[t][mt], bh[nt]);
        }
        __syncthreads();
    }

    const int er = lane >> 2;
    const int ec = (lane & 3) * 2;
#pragma unroll
    for (int mt = 0; mt < 2; mt++) {
        const int row0 = bm + warp_m + mt * 16 + er;
#pragma unroll
        for (int nt = 0; nt < 8; nt++) {
            const int col = bn + warp_n + nt * 8 + ec;
            *(float2*)(C + (size_t)row0 * ldc + col) =
                make_float2(acc[mt][nt][0], acc[mt][nt][1]);
            *(float2*)(C + (size_t)(row0 + 8) * ldc + col) =
                make_float2(acc[mt][nt][2], acc[mt][nt][3]);
        }
    }
}

// ---------------------------------------------------------------------------
// Scan pass A: per-(batch, chunk, channel) local reduction with zero init.
// ---------------------------------------------------------------------------
__global__ void scan_passA(const float* __restrict__ td)
{
    const int d = threadIdx.x;
    const int c = blockIdx.x;
    const int b = blockIdx.y;

    const float decay = expf(-expf(td[d]));

    const size_t base = ((size_t)b * SEQ + (size_t)c * CHUNK_L) * NKVR + d;
    float s = 0.0f;
#pragma unroll 4
    for (int t = 0; t < CHUNK_L; t++) {
        const size_t idx = base + (size_t)t * NKVR;
        float kv = g_kvr[idx] * g_kvr[idx + DIM];
        s = fmaf(decay, s, kv);
    }
    g_chunk_sum[((size_t)b * NCHUNK + c) * DIM + d] = s;
}

// ---------------------------------------------------------------------------
// Scan pass B: sequential carry across chunks.
// ---------------------------------------------------------------------------
__global__ void scan_passB(const float* __restrict__ td)
{
    const int d = threadIdx.x;
    const int b = blockIdx.x;

    const float decayL = expf(-(float)CHUNK_L * expf(td[d]));

    float carry = 0.0f;
#pragma unroll
    for (int c = 0; c < NCHUNK; c++) {
        const size_t idx = ((size_t)b * NCHUNK + c) * DIM + d;
        g_state_in[idx] = carry;
        carry = fmaf(decayL, carry, g_chunk_sum[idx]);
    }
}

// ---------------------------------------------------------------------------
// Scan pass C: replay with correct incoming state; writes hi/lo fp16 split of
// sigmoid(r)*wkv (input to the final GEMM).
// ---------------------------------------------------------------------------
__global__ void scan_passC(const float* __restrict__ td,
                           const float* __restrict__ tf)
{
    const int d = threadIdx.x;
    const int c = blockIdx.x;
    const int b = blockIdx.y;

    const float decay = expf(-expf(td[d]));
    const float eu    = expf(tf[d]);

    float state = g_state_in[((size_t)b * NCHUNK + c) * DIM + d];

    const size_t rowbase = (size_t)b * SEQ + (size_t)c * CHUNK_L;
#pragma unroll 4
    for (int t = 0; t < CHUNK_L; t++) {
        const size_t row = rowbase + t;
        const size_t src = row * NKVR + d;
        float kv  = g_kvr[src] * g_kvr[src + DIM];
        float wkv = fmaf(eu, kv, state);
        state = fmaf(decay, state, kv);
        float rp = g_kvr[src + 2 * DIM];
        float rs = 1.0f / (1.0f + expf(-rp));
        float o = rs * wkv;
        __half h = __float2half_rn(o);
        __half l = __float2half_rn(o - __half2float(h));
        const size_t dst = row * DIM + d;
        g_ohi[dst] = h;
        g_olo[dst] = l;
    }
}

// ---------------------------------------------------------------------------
// Launch
// ---------------------------------------------------------------------------
extern "C" void kernel_launch(void* const* d_in, const int* in_sizes, int n_in,
                              void* d_out, int out_size)
{
    const float* x  = (const float*)d_in[0];
    const float* Wk = (const float*)d_in[1];
    const float* Wv = (const float*)d_in[2];
    const float* Wr = (const float*)d_in[3];
    const float* Wo = (const float*)d_in[4];
    const float* td = (const float*)d_in[5];
    const float* tf = (const float*)d_in[6];
    float* out = (float*)d_out;

    float* kvr;
    cudaGetSymbolAddress((void**)&kvr, g_kvr);
    __half *xhi, *wh, *ohi, *olo;
    cudaGetSymbolAddress((void**)&xhi, g_xhi);
    cudaGetSymbolAddress((void**)&wh,  g_wh);
    cudaGetSymbolAddress((void**)&ohi, g_ohi);
    cudaGetSymbolAddress((void**)&olo, g_olo);

    const int smem1 = NSTAGE * 2 * TILE_B;   // 49152
    const int smem2 = NSTAGE * 3 * TILE_B;   // 73728
    cudaFuncSetAttribute(gemm_fp16t<1>,
                         cudaFuncAttributeMaxDynamicSharedMemorySize, smem1);
    cudaFuncSetAttribute(gemm_fp16t<2>,
                         cudaFuncAttributeMaxDynamicSharedMemorySize, smem2);

    // Converts: x -> fp16 (single), weights -> fp16 (Wk|Wv|Wr|Wo concat)
    convert_h<<<2048, 256>>>(x, xhi, MROWS * DIM / 4);
    const float* Ws[4] = {Wk, Wv, Wr, Wo};
    for (int i = 0; i < 4; i++)
        convert_h<<<1024, 256>>>(Ws[i], wh + (size_t)i * DIM * DIM, DIM * DIM / 4);

    // Fused k|v|r projection: pure fp16 (1 A term)
    dim3 ggrid_kvr(NKVR / BN, MROWS / BM);   // (24, 128)
    gemm_fp16t<1><<<ggrid_kvr, GTHREADS, smem1>>>(xhi, nullptr, wh, kvr, NKVR);

    // Chunked linear scan
    dim3 sgrid(NCHUNK, BATCH);
    scan_passA<<<sgrid, DIM>>>(td);
    scan_passB<<<BATCH, DIM>>>(td);
    scan_passC<<<sgrid, DIM>>>(td, tf);

    // Output projection: fp16x2 (hi+lo A) for accuracy headroom
    dim3 ggrid_o(DIM / BN, MROWS / BM);      // (8, 128)
    gemm_fp16t<2><<<ggrid_o, GTHREADS, smem2>>>(ohi, olo,
        wh + 3 * (size_t)DIM * DIM, out, DIM);
}

// round 10
// speedup vs baseline: 6.5634x; 1.1547x over previous
#include <cuda_runtime.h>
#include <cuda_fp16.h>
#include <cstdint>
#include <math.h>

// Problem constants
#define BATCH 4
#define SEQ   4096
#define DIM   1024
#define MROWS (BATCH * SEQ)          // 16384
#define NKVR  (3 * DIM)              // 3072 fused output channels

// Scan chunking
#define CHUNK_L 128
#define NCHUNK  (SEQ / CHUNK_L)      // 32

// GEMM tiling
#define BM 128
#define BN 128
#define BK 32                         // fp16 K elems per stage (64B rows)
#define KCHUNKS (DIM / BK)            // 32
#define NSTAGE 3
#define GTHREADS 256

#define TILE_B  (128 * BK * 2)        // 8192 B per fp16 tile
#define STAGE_B (2 * TILE_B)          // A, B tiles = 16384 B
#define SMEM_TOTAL (NSTAGE * STAGE_B) // 49152 B

// ---------------------------------------------------------------------------
// Scratch (no cudaMalloc allowed)
// ---------------------------------------------------------------------------
__device__ float g_kvr[MROWS * NKVR];            // fused k|v|r outputs
__device__ float g_chunk_sum[BATCH * NCHUNK * DIM];
__device__ float g_state_in[BATCH * NCHUNK * DIM];

__device__ __half g_xhi[MROWS * DIM];
__device__ __half g_wh[4 * DIM * DIM];           // Wk|Wv|Wr|Wo fp16
__device__ __half g_ohi[MROWS * DIM];            // wo_in fp16

// ---------------------------------------------------------------------------
// Helpers
// ---------------------------------------------------------------------------
__device__ __forceinline__ uint32_t smem_u32(const void* p) {
    uint32_t a;
    asm("{ .reg .u64 t; cvta.to.shared.u64 t, %1; cvt.u32.u64 %0, t; }"
        : "=r"(a) : "l"(p));
    return a;
}

__device__ __forceinline__ void cp_async16(uint32_t dst, const void* src) {
    asm volatile("cp.async.cg.shared.global [%0], [%1], 16;"
                 :: "r"(dst), "l"(src) : "memory");
}
__device__ __forceinline__ void cp_commit() {
    asm volatile("cp.async.commit_group;" ::: "memory");
}
__device__ __forceinline__ void cp_wait1() {
    asm volatile("cp.async.wait_group 1;" ::: "memory");
}

__device__ __forceinline__ void ldmx4(uint32_t* r, uint32_t addr) {
    asm volatile("ldmatrix.sync.aligned.m8n8.x4.shared.b16 {%0,%1,%2,%3}, [%4];"
                 : "=r"(r[0]), "=r"(r[1]), "=r"(r[2]), "=r"(r[3]) : "r"(addr));
}

__device__ __forceinline__ void mma_f16(float* d, const uint32_t* a,
                                        const uint32_t* b) {
    asm volatile(
        "mma.sync.aligned.m16n8k16.row.col.f32.f16.f16.f32 "
        "{%0,%1,%2,%3}, {%4,%5,%6,%7}, {%8,%9}, {%0,%1,%2,%3};"
        : "+f"(d[0]), "+f"(d[1]), "+f"(d[2]), "+f"(d[3])
        : "r"(a[0]), "r"(a[1]), "r"(a[2]), "r"(a[3]), "r"(b[0]), "r"(b[1]));
}

// SMEM swizzle for 64B rows (conflict-free ldmatrix)
__device__ __forceinline__ uint32_t sw_off(uint32_t r, uint32_t kb) {
    return r * 64 + (kb ^ (((r >> 1) & 3) << 4));
}

// ---------------------------------------------------------------------------
// Converts
// ---------------------------------------------------------------------------
__global__ void convert_h(const float* __restrict__ src,
                          __half* __restrict__ dst, int n4)
{
    for (int i = blockIdx.x * blockDim.x + threadIdx.x; i < n4;
         i += gridDim.x * blockDim.x) {
        float4 f = ((const float4*)src)[i];
        __half2 p0 = __floats2half2_rn(f.x, f.y);
        __half2 p1 = __floats2half2_rn(f.z, f.w);
        ((uint2*)dst)[i] = make_uint2(*(uint32_t*)&p0, *(uint32_t*)&p1);
    }
}

// All four weights in one launch: blockIdx.y selects the source matrix.
__global__ void convert_w4(const float* __restrict__ w0,
                           const float* __restrict__ w1,
                           const float* __restrict__ w2,
                           const float* __restrict__ w3,
                           __half* __restrict__ dst)
{
    const int n4 = DIM * DIM / 4;
    const float* src = (blockIdx.y == 0) ? w0 : (blockIdx.y == 1) ? w1
                      : (blockIdx.y == 2) ? w2 : w3;
    __half* d = dst + (size_t)blockIdx.y * DIM * DIM;
    for (int i = blockIdx.x * blockDim.x + threadIdx.x; i < n4;
         i += gridDim.x * blockDim.x) {
        float4 f = ((const float4*)src)[i];
        __half2 p0 = __floats2half2_rn(f.x, f.y);
        __half2 p1 = __floats2half2_rn(f.z, f.w);
        ((uint2*)d)[i] = make_uint2(*(uint32_t*)&p0, *(uint32_t*)&p1);
    }
}

// ---------------------------------------------------------------------------
// fp16 NT GEMM via mma.sync: C[m][n] = sum_k A[m][k]*B[n][k]
// grid (N/BN, MROWS/BM), 256 threads, 3-stage cp.async pipeline.
// ---------------------------------------------------------------------------
__global__ __launch_bounds__(GTHREADS, 2)
void gemm_fp16(const __half* __restrict__ Ah,
               const __half* __restrict__ Bh,
               float* __restrict__ C, int ldc)
{
    extern __shared__ char smem[];
    const uint32_t sb = smem_u32(smem);
    const int tid = threadIdx.x;
    const int wid = tid >> 5;
    const int lane = tid & 31;
    const int bm = blockIdx.y * BM;
    const int bn = blockIdx.x * BN;

    const int warp_m = (wid >> 1) * 32;   // 0,32,64,96
    const int warp_n = (wid & 1) * 64;    // 0,64

    auto issue_stage = [&](int c, int s) {
        const uint32_t stage = sb + s * STAGE_B;
#pragma unroll
        for (int tile = 0; tile < 2; tile++) {
            const __half* src = tile ? Bh : Ah;
            const int rowbase = tile ? bn : bm;
#pragma unroll
            for (int i = 0; i < 2; i++) {
                const int idx = i * 256 + tid;   // 0..511
                const uint32_t r = idx >> 2;
                const uint32_t kq = (idx & 3) * 16;
                const uint32_t dst = stage + tile * TILE_B + sw_off(r, kq);
                const char* sp = (const char*)(src + (size_t)(rowbase + r) * DIM
                                               + c * BK) + kq;
                cp_async16(dst, sp);
            }
        }
    };

    issue_stage(0, 0); cp_commit();
    issue_stage(1, 1); cp_commit();

    float acc[2][8][4];
#pragma unroll
    for (int mt = 0; mt < 2; mt++)
#pragma unroll
        for (int nt = 0; nt < 8; nt++)
#pragma unroll
            for (int j = 0; j < 4; j++) acc[mt][nt][j] = 0.0f;

    const int gA = lane >> 3, rlA = lane & 7;
    const int a_row_off = (gA & 1) * 8 + rlA;
    const int a_kb_off = (gA >> 1) * 16;
    const int b_row_off = (gA >> 1) * 8 + rlA;
    const int b_kb_off = (gA & 1) * 16;

    for (int c = 0; c < KCHUNKS; c++) {
        cp_wait1();
        __syncthreads();
        if (c + 2 < KCHUNKS) issue_stage(c + 2, (c + 2) % NSTAGE);
        cp_commit();

        const uint32_t stage = sb + (c % NSTAGE) * STAGE_B;
        const uint32_t sB = stage + TILE_B;

#pragma unroll
        for (int ks = 0; ks < 2; ks++) {
            const uint32_t kbase = ks * 32;
            uint32_t a[2][4];
#pragma unroll
            for (int mt = 0; mt < 2; mt++) {
                const uint32_t r = warp_m + mt * 16 + a_row_off;
                const uint32_t kb = kbase + a_kb_off;
                ldmx4(a[mt], stage + sw_off(r, kb));
            }
            uint32_t bh[8][2];
#pragma unroll
            for (int p = 0; p < 4; p++) {
                const uint32_t n = warp_n + p * 16 + b_row_off;
                const uint32_t kb = kbase + b_kb_off;
                uint32_t t4[4];
                ldmx4(t4, sB + sw_off(n, kb));
                bh[2 * p][0] = t4[0]; bh[2 * p][1] = t4[1];
                bh[2 * p + 1][0] = t4[2]; bh[2 * p + 1][1] = t4[3];
            }
#pragma unroll
            for (int mt = 0; mt < 2; mt++)
#pragma unroll
                for (int nt = 0; nt < 8; nt++)
                    mma_f16(acc[mt][nt], a[mt], bh[nt]);
        }
        __syncthreads();
    }

    const int er = lane >> 2;
    const int ec = (lane & 3) * 2;
#pragma unroll
    for (int mt = 0; mt < 2; mt++) {
        const int row0 = bm + warp_m + mt * 16 + er;
#pragma unroll
        for (int nt = 0; nt < 8; nt++) {
            const int col = bn + warp_n + nt * 8 + ec;
            *(float2*)(C + (size_t)row0 * ldc + col) =
                make_float2(acc[mt][nt][0], acc[mt][nt][1]);
            *(float2*)(C + (size_t)(row0 + 8) * ldc + col) =
                make_float2(acc[mt][nt][2], acc[mt][nt][3]);
        }
    }
}

// ---------------------------------------------------------------------------
// Scan pass A: per-(batch, chunk, channel) local reduction with zero init.
// ---------------------------------------------------------------------------
__global__ void scan_passA(const float* __restrict__ td)
{
    const int d = threadIdx.x;
    const int c = blockIdx.x;
    const int b = blockIdx.y;

    const float decay = expf(-expf(td[d]));

    const size_t base = ((size_t)b * SEQ + (size_t)c * CHUNK_L) * NKVR + d;
    float s = 0.0f;
#pragma unroll 4
    for (int t = 0; t < CHUNK_L; t++) {
        const size_t idx = base + (size_t)t * NKVR;
        float kv = g_kvr[idx] * g_kvr[idx + DIM];
        s = fmaf(decay, s, kv);
    }
    g_chunk_sum[((size_t)b * NCHUNK + c) * DIM + d] = s;
}

// ---------------------------------------------------------------------------
// Scan pass B: sequential carry across chunks.
// ---------------------------------------------------------------------------
__global__ void scan_passB(const float* __restrict__ td)
{
    const int d = threadIdx.x;
    const int b = blockIdx.x;

    const float decayL = expf(-(float)CHUNK_L * expf(td[d]));

    float carry = 0.0f;
#pragma unroll
    for (int c = 0; c < NCHUNK; c++) {
        const size_t idx = ((size_t)b * NCHUNK + c) * DIM + d;
        g_state_in[idx] = carry;
        carry = fmaf(decayL, carry, g_chunk_sum[idx]);
    }
}

// ---------------------------------------------------------------------------
// Scan pass C: replay with correct incoming state; writes fp16
// sigmoid(r)*wkv (input to the final GEMM).
// ---------------------------------------------------------------------------
__global__ void scan_passC(const float* __restrict__ td,
                           const float* __restrict__ tf)
{
    const int d = threadIdx.x;
    const int c = blockIdx.x;
    const int b = blockIdx.y;

    const float decay = expf(-expf(td[d]));
    const float eu    = expf(tf[d]);

    float state = g_state_in[((size_t)b * NCHUNK + c) * DIM + d];

    const size_t rowbase = (size_t)b * SEQ + (size_t)c * CHUNK_L;
#pragma unroll 4
    for (int t = 0; t < CHUNK_L; t++) {
        const size_t row = rowbase + t;
        const size_t src = row * NKVR + d;
        float kv  = g_kvr[src] * g_kvr[src + DIM];
        float wkv = fmaf(eu, kv, state);
        state = fmaf(decay, state, kv);
        float rp = g_kvr[src + 2 * DIM];
        float rs = 1.0f / (1.0f + expf(-rp));
        g_ohi[row * DIM + d] = __float2half_rn(rs * wkv);
    }
}

// ---------------------------------------------------------------------------
// Launch
// ---------------------------------------------------------------------------
extern "C" void kernel_launch(void* const* d_in, const int* in_sizes, int n_in,
                              void* d_out, int out_size)
{
    const float* x  = (const float*)d_in[0];
    const float* Wk = (const float*)d_in[1];
    const float* Wv = (const float*)d_in[2];
    const float* Wr = (const float*)d_in[3];
    const float* Wo = (const float*)d_in[4];
    const float* td = (const float*)d_in[5];
    const float* tf = (const float*)d_in[6];
    float* out = (float*)d_out;

    float* kvr;
    cudaGetSymbolAddress((void**)&kvr, g_kvr);
    __half *xhi, *wh, *ohi;
    cudaGetSymbolAddress((void**)&xhi, g_xhi);
    cudaGetSymbolAddress((void**)&wh,  g_wh);
    cudaGetSymbolAddress((void**)&ohi, g_ohi);

    cudaFuncSetAttribute(gemm_fp16,
                         cudaFuncAttributeMaxDynamicSharedMemorySize, SMEM_TOTAL);

    // Converts: x -> fp16, all four weights in one launch
    convert_h<<<2048, 256>>>(x, xhi, MROWS * DIM / 4);
    convert_w4<<<dim3(256, 4), 256>>>(Wk, Wv, Wr, Wo, wh);

    // Fused k|v|r projection: pure fp16
    dim3 ggrid_kvr(NKVR / BN, MROWS / BM);   // (24, 128)
    gemm_fp16<<<ggrid_kvr, GTHREADS, SMEM_TOTAL>>>(xhi, wh, kvr, NKVR);

    // Chunked linear scan
    dim3 sgrid(NCHUNK, BATCH);
    scan_passA<<<sgrid, DIM>>>(td);
    scan_passB<<<BATCH, DIM>>>(td);
    scan_passC<<<sgrid, DIM>>>(td, tf);

    // Output projection: pure fp16
    dim3 ggrid_o(DIM / BN, MROWS / BM);      // (8, 128)
    gemm_fp16<<<ggrid_o, GTHREADS, SMEM_TOTAL>>>(ohi,
        wh + 3 * (size_t)DIM * DIM, out, DIM);
}

// round 14
// speedup vs baseline: 7.2828x; 1.1096x over previous
#include <cuda_runtime.h>
#include <cuda_fp16.h>
#include <cstdint>
#include <math.h>

// Problem constants
#define BATCH 4
#define SEQ   4096
#define DIM   1024
#define MROWS (BATCH * SEQ)          // 16384
#define NKVR  (3 * DIM)              // 3072 fused output channels

// Scan chunking
#define CHUNK_L 64
#define NCHUNK  (SEQ / CHUNK_L)      // 64

// GEMM tiling
#define BM 128
#define BN 128
#define BK 32                         // fp16 K elems per stage (64B rows)
#define KCHUNKS (DIM / BK)            // 32
#define NSTAGE 3
#define GTHREADS 256

#define TILE_B  (128 * BK * 2)        // 8192 B per fp16 tile
#define STAGE_B (2 * TILE_B)          // A, B tiles = 16384 B
#define SMEM_TOTAL (NSTAGE * STAGE_B) // 49152 B

// ---------------------------------------------------------------------------
// Scratch (no cudaMalloc allowed)
// ---------------------------------------------------------------------------
__device__ __half g_kvrh[MROWS * NKVR];          // fused k|v|r outputs (fp16)
__device__ float g_chunk_sum[BATCH * NCHUNK * DIM];
__device__ float g_state_in[BATCH * NCHUNK * DIM];

__device__ __half g_xhi[MROWS * DIM];
__device__ __half g_wh[4 * DIM * DIM];           // Wk|Wv|Wr|Wo fp16
__device__ __half g_ohi[MROWS * DIM];            // wo_in fp16

// ---------------------------------------------------------------------------
// Helpers
// ---------------------------------------------------------------------------
__device__ __forceinline__ uint32_t smem_u32(const void* p) {
    uint32_t a;
    asm("{ .reg .u64 t; cvta.to.shared.u64 t, %1; cvt.u32.u64 %0, t; }"
        : "=r"(a) : "l"(p));
    return a;
}

__device__ __forceinline__ void cp_async16(uint32_t dst, const void* src) {
    asm volatile("cp.async.cg.shared.global [%0], [%1], 16;"
                 :: "r"(dst), "l"(src) : "memory");
}
__device__ __forceinline__ void cp_commit() {
    asm volatile("cp.async.commit_group;" ::: "memory");
}
__device__ __forceinline__ void cp_wait1() {
    asm volatile("cp.async.wait_group 1;" ::: "memory");
}

__device__ __forceinline__ void ldmx4(uint32_t* r, uint32_t addr) {
    asm volatile("ldmatrix.sync.aligned.m8n8.x4.shared.b16 {%0,%1,%2,%3}, [%4];"
                 : "=r"(r[0]), "=r"(r[1]), "=r"(r[2]), "=r"(r[3]) : "r"(addr));
}

__device__ __forceinline__ void mma_f16(float* d, const uint32_t* a,
                                        const uint32_t* b) {
    asm volatile(
        "mma.sync.aligned.m16n8k16.row.col.f32.f16.f16.f32 "
        "{%0,%1,%2,%3}, {%4,%5,%6,%7}, {%8,%9}, {%0,%1,%2,%3};"
        : "+f"(d[0]), "+f"(d[1]), "+f"(d[2]), "+f"(d[3])
        : "r"(a[0]), "r"(a[1]), "r"(a[2]), "r"(a[3]), "r"(b[0]), "r"(b[1]));
}

// SMEM swizzle for 64B rows (conflict-free ldmatrix)
__device__ __forceinline__ uint32_t sw_off(uint32_t r, uint32_t kb) {
    return r * 64 + (kb ^ (((r >> 1) & 3) << 4));
}

// ---------------------------------------------------------------------------
// Converts
// ---------------------------------------------------------------------------
__global__ void convert_h(const float* __restrict__ src,
                          __half* __restrict__ dst, int n4)
{
    for (int i = blockIdx.x * blockDim.x + threadIdx.x; i < n4;
         i += gridDim.x * blockDim.x) {
        float4 f = ((const float4*)src)[i];
        __half2 p0 = __floats2half2_rn(f.x, f.y);
        __half2 p1 = __floats2half2_rn(f.z, f.w);
        ((uint2*)dst)[i] = make_uint2(*(uint32_t*)&p0, *(uint32_t*)&p1);
    }
}

// All four weights in one launch: blockIdx.y selects the source matrix.
__global__ void convert_w4(const float* __restrict__ w0,
                           const float* __restrict__ w1,
                           const float* __restrict__ w2,
                           const float* __restrict__ w3,
                           __half* __restrict__ dst)
{
    const int n4 = DIM * DIM / 4;
    const float* src = (blockIdx.y == 0) ? w0 : (blockIdx.y == 1) ? w1
                      : (blockIdx.y == 2) ? w2 : w3;
    __half* d = dst + (size_t)blockIdx.y * DIM * DIM;
    for (int i = blockIdx.x * blockDim.x + threadIdx.x; i < n4;
         i += gridDim.x * blockDim.x) {
        float4 f = ((const float4*)src)[i];
        __half2 p0 = __floats2half2_rn(f.x, f.y);
        __half2 p1 = __floats2half2_rn(f.z, f.w);
        ((uint2*)d)[i] = make_uint2(*(uint32_t*)&p0, *(uint32_t*)&p1);
    }
}

// ---------------------------------------------------------------------------
// fp16 NT GEMM via mma.sync: C[m][n] = sum_k A[m][k]*B[n][k]
// OutT = float (fp32 out) or __half (fp16 out).
// grid (N/BN, MROWS/BM), 256 threads, 3-stage cp.async pipeline.
// ---------------------------------------------------------------------------
template <typename OutT>
__global__ __launch_bounds__(GTHREADS, 2)
void gemm_fp16(const __half* __restrict__ Ah,
               const __half* __restrict__ Bh,
               OutT* __restrict__ C, int ldc)
{
    extern __shared__ char smem[];
    const uint32_t sb = smem_u32(smem);
    const int tid = threadIdx.x;
    const int wid = tid >> 5;
    const int lane = tid & 31;
    const int bm = blockIdx.y * BM;
    const int bn = blockIdx.x * BN;

    const int warp_m = (wid >> 1) * 32;   // 0,32,64,96
    const int warp_n = (wid & 1) * 64;    // 0,64

    auto issue_stage = [&](int c, int s) {
        const uint32_t stage = sb + s * STAGE_B;
#pragma unroll
        for (int tile = 0; tile < 2; tile++) {
            const __half* src = tile ? Bh : Ah;
            const int rowbase = tile ? bn : bm;
#pragma unroll
            for (int i = 0; i < 2; i++) {
                const int idx = i * 256 + tid;   // 0..511
                const uint32_t r = idx >> 2;
                const uint32_t kq = (idx & 3) * 16;
                const uint32_t dst = stage + tile * TILE_B + sw_off(r, kq);
                const char* sp = (const char*)(src + (size_t)(rowbase + r) * DIM
                                               + c * BK) + kq;
                cp_async16(dst, sp);
            }
        }
    };

    issue_stage(0, 0); cp_commit();
    issue_stage(1, 1); cp_commit();

    float acc[2][8][4];
#pragma unroll
    for (int mt = 0; mt < 2; mt++)
#pragma unroll
        for (int nt = 0; nt < 8; nt++)
#pragma unroll
            for (int j = 0; j < 4; j++) acc[mt][nt][j] = 0.0f;

    const int gA = lane >> 3, rlA = lane & 7;
    const int a_row_off = (gA & 1) * 8 + rlA;
    const int a_kb_off = (gA >> 1) * 16;
    const int b_row_off = (gA >> 1) * 8 + rlA;
    const int b_kb_off = (gA & 1) * 16;

    for (int c = 0; c < KCHUNKS; c++) {
        cp_wait1();
        __syncthreads();
        if (c + 2 < KCHUNKS) issue_stage(c + 2, (c + 2) % NSTAGE);
        cp_commit();

        const uint32_t stage = sb + (c % NSTAGE) * STAGE_B;
        const uint32_t sB = stage + TILE_B;

#pragma unroll
        for (int ks = 0; ks < 2; ks++) {
            const uint32_t kbase = ks * 32;
            uint32_t a[2][4];
#pragma unroll
            for (int mt = 0; mt < 2; mt++) {
                const uint32_t r = warp_m + mt * 16 + a_row_off;
                const uint32_t kb = kbase + a_kb_off;
                ldmx4(a[mt], stage + sw_off(r, kb));
            }
            uint32_t bh[8][2];
#pragma unroll
            for (int p = 0; p < 4; p++) {
                const uint32_t n = warp_n + p * 16 + b_row_off;
                const uint32_t kb = kbase + b_kb_off;
                uint32_t t4[4];
                ldmx4(t4, sB + sw_off(n, kb));
                bh[2 * p][0] = t4[0]; bh[2 * p][1] = t4[1];
                bh[2 * p + 1][0] = t4[2]; bh[2 * p + 1][1] = t4[3];
            }
#pragma unroll
            for (int mt = 0; mt < 2; mt++)
#pragma unroll
                for (int nt = 0; nt < 8; nt++)
                    mma_f16(acc[mt][nt], a[mt], bh[nt]);
        }
        __syncthreads();
    }

    const int er = lane >> 2;
    const int ec = (lane & 3) * 2;
#pragma unroll
    for (int mt = 0; mt < 2; mt++) {
        const int row0 = bm + warp_m + mt * 16 + er;
#pragma unroll
        for (int nt = 0; nt < 8; nt++) {
            const int col = bn + warp_n + nt * 8 + ec;
            if constexpr (sizeof(OutT) == 4) {
                *(float2*)((float*)C + (size_t)row0 * ldc + col) =
                    make_float2(acc[mt][nt][0], acc[mt][nt][1]);
                *(float2*)((float*)C + (size_t)(row0 + 8) * ldc + col) =
                    make_float2(acc[mt][nt][2], acc[mt][nt][3]);
            } else {
                *(__half2*)((__half*)C + (size_t)row0 * ldc + col) =
                    __floats2half2_rn(acc[mt][nt][0], acc[mt][nt][1]);
                *(__half2*)((__half*)C + (size_t)(row0 + 8) * ldc + col) =
                    __floats2half2_rn(acc[mt][nt][2], acc[mt][nt][3]);
            }
        }
    }
}

// ---------------------------------------------------------------------------
// Scan pass A: 2 channels/thread (half2), per-chunk local reduction.
// grid (NCHUNK, BATCH), block 512.
// ---------------------------------------------------------------------------
__global__ void scan_passA(const float* __restrict__ td)
{
    const int d0 = 2 * threadIdx.x;
    const int c = blockIdx.x;
    const int b = blockIdx.y;

    const float dec0 = expf(-expf(td[d0]));
    const float dec1 = expf(-expf(td[d0 + 1]));

    const size_t base = ((size_t)b * SEQ + (size_t)c * CHUNK_L) * NKVR + d0;
    float s0 = 0.0f, s1 = 0.0f;
#pragma unroll 4
    for (int t = 0; t < CHUNK_L; t++) {
        const size_t idx = base + (size_t)t * NKVR;
        float2 k2 = __half22float2(*(const __half2*)(g_kvrh + idx));
        float2 v2 = __half22float2(*(const __half2*)(g_kvrh + idx + DIM));
        s0 = fmaf(dec0, s0, k2.x * v2.x);
        s1 = fmaf(dec1, s1, k2.y * v2.y);
    }
    *(float2*)(g_chunk_sum + ((size_t)b * NCHUNK + c) * DIM + d0) =
        make_float2(s0, s1);
}

// ---------------------------------------------------------------------------
// Scan pass B: sequential carry across chunks. grid BATCH, block 512.
// ---------------------------------------------------------------------------
__global__ void scan_passB(const float* __restrict__ td)
{
    const int d0 = 2 * threadIdx.x;
    const int b = blockIdx.x;

    const float dL0 = expf(-(float)CHUNK_L * expf(td[d0]));
    const float dL1 = expf(-(float)CHUNK_L * expf(td[d0 + 1]));

    float c0 = 0.0f, c1 = 0.0f;
#pragma unroll
    for (int c = 0; c < NCHUNK; c++) {
        const size_t idx = ((size_t)b * NCHUNK + c) * DIM + d0;
        *(float2*)(g_state_in + idx) = make_float2(c0, c1);
        float2 s = *(const float2*)(g_chunk_sum + idx);
        c0 = fmaf(dL0, c0, s.x);
        c1 = fmaf(dL1, c1, s.y);
    }
}

// ---------------------------------------------------------------------------
// Scan pass C: replay with incoming state; writes fp16 sigmoid(r)*wkv.
// grid (NCHUNK, BATCH), block 512.
// ---------------------------------------------------------------------------
__global__ void scan_passC(const float* __restrict__ td,
                           const float* __restrict__ tf)
{
    const int d0 = 2 * threadIdx.x;
    const int c = blockIdx.x;
    const int b = blockIdx.y;

    const float dec0 = expf(-expf(td[d0]));
    const float dec1 = expf(-expf(td[d0 + 1]));
    const float eu0  = expf(tf[d0]);
    const float eu1  = expf(tf[d0 + 1]);

    float2 st = *(const float2*)(g_state_in + ((size_t)b * NCHUNK + c) * DIM + d0);

    const size_t rowbase = (size_t)b * SEQ + (size_t)c * CHUNK_L;
#pragma unroll 4
    for (int t = 0; t < CHUNK_L; t++) {
        const size_t row = rowbase + t;
        const size_t src = row * NKVR + d0;
        float2 k2 = __half22float2(*(const __half2*)(g_kvrh + src));
        float2 v2 = __half22float2(*(const __half2*)(g_kvrh + src + DIM));
        float2 r2 = __half22float2(*(const __half2*)(g_kvrh + src + 2 * DIM));
        float kv0 = k2.x * v2.x, kv1 = k2.y * v2.y;
        float wkv0 = fmaf(eu0, kv0, st.x);
        float wkv1 = fmaf(eu1, kv1, st.y);
        st.x = fmaf(dec0, st.x, kv0);
        st.y = fmaf(dec1, st.y, kv1);
        float rs0 = 1.0f / (1.0f + expf(-r2.x));
        float rs1 = 1.0f / (1.0f + expf(-r2.y));
        *(__half2*)(g_ohi + row * DIM + d0) =
            __floats2half2_rn(rs0 * wkv0, rs1 * wkv1);
    }
}

// ---------------------------------------------------------------------------
// Launch
// ---------------------------------------------------------------------------
extern "C" void kernel_launch(void* const* d_in, const int* in_sizes, int n_in,
                              void* d_out, int out_size)
{
    const float* x  = (const float*)d_in[0];
    const float* Wk = (const float*)d_in[1];
    const float* Wv = (const float*)d_in[2];
    const float* Wr = (const float*)d_in[3];
    const float* Wo = (const float*)d_in[4];
    const float* td = (const float*)d_in[5];
    const float* tf = (const float*)d_in[6];
    float* out = (float*)d_out;

    __half *kvrh, *xhi, *wh, *ohi;
    cudaGetSymbolAddress((void**)&kvrh, g_kvrh);
    cudaGetSymbolAddress((void**)&xhi,  g_xhi);
    cudaGetSymbolAddress((void**)&wh,   g_wh);
    cudaGetSymbolAddress((void**)&ohi,  g_ohi);

    cudaFuncSetAttribute(gemm_fp16<__half>,
                         cudaFuncAttributeMaxDynamicSharedMemorySize, SMEM_TOTAL);
    cudaFuncSetAttribute(gemm_fp16<float>,
                         cudaFuncAttributeMaxDynamicSharedMemorySize, SMEM_TOTAL);

    // Converts: x -> fp16, all four weights in one launch
    convert_h<<<2048, 256>>>(x, xhi, MROWS * DIM / 4);
    convert_w4<<<dim3(256, 4), 256>>>(Wk, Wv, Wr, Wo, wh);

    // Fused k|v|r projection: pure fp16, fp16 output
    dim3 ggrid_kvr(NKVR / BN, MROWS / BM);   // (24, 128)
    gemm_fp16<__half><<<ggrid_kvr, GTHREADS, SMEM_TOTAL>>>(xhi, wh, kvrh, NKVR);

    // Chunked linear scan
    dim3 sgrid(NCHUNK, BATCH);
    scan_passA<<<sgrid, DIM / 2>>>(td);
    scan_passB<<<BATCH, DIM / 2>>>(td);
    scan_passC<<<sgrid, DIM / 2>>>(td, tf);

    // Output projection: pure fp16, fp32 output
    dim3 ggrid_o(DIM / BN, MROWS / BM);      // (8, 128)
    gemm_fp16<float><<<ggrid_o, GTHREADS, SMEM_TOTAL>>>(ohi,
        wh + 3 * (size_t)DIM * DIM, out, DIM);
}

// round 16
// speedup vs baseline: 7.3156x; 1.0045x over previous
#include <cuda_runtime.h>
#include <cuda_fp16.h>
#include <cstdint>
#include <math.h>

// Problem constants
#define BATCH 4
#define SEQ   4096
#define DIM   1024
#define MROWS (BATCH * SEQ)          // 16384
#define NKVR  (3 * DIM)              // 3072 fused output channels (2048 kv-interleaved + 1024 r)

// Scan chunking
#define CHUNK_L 64
#define NCHUNK  (SEQ / CHUNK_L)      // 64

// GEMM tiling
#define BM 128
#define BN 128
#define BK 32                         // fp16 K elems per stage (64B rows)
#define KCHUNKS (DIM / BK)            // 32
#define NSTAGE 3
#define GTHREADS 256

#define TILE_B  (128 * BK * 2)        // 8192 B per fp16 tile
#define STAGE_B (2 * TILE_B)          // A, B tiles = 16384 B
#define SMEM_TOTAL (NSTAGE * STAGE_B) // 49152 B

// ---------------------------------------------------------------------------
// Scratch (no cudaMalloc allowed)
// ---------------------------------------------------------------------------
__device__ __half g_kvh[MROWS * DIM];            // kv = k*v products (fp16)
__device__ __half g_rh[MROWS * DIM];             // r pre-sigmoid (fp16)
__device__ float g_chunk_sum[BATCH * NCHUNK * DIM];
__device__ float g_state_in[BATCH * NCHUNK * DIM];

__device__ __half g_xhi[MROWS * DIM];
__device__ __half g_wh[4 * DIM * DIM];           // [WkWv interleaved | Wr | Wo]
__device__ __half g_ohi[MROWS * DIM];            // wo_in fp16

// ---------------------------------------------------------------------------
// Helpers
// ---------------------------------------------------------------------------
__device__ __forceinline__ uint32_t smem_u32(const void* p) {
    uint32_t a;
    asm("{ .reg .u64 t; cvta.to.shared.u64 t, %1; cvt.u32.u64 %0, t; }"
        : "=r"(a) : "l"(p));
    return a;
}

__device__ __forceinline__ void cp_async16(uint32_t dst, const void* src) {
    asm volatile("cp.async.cg.shared.global [%0], [%1], 16;"
                 :: "r"(dst), "l"(src) : "memory");
}
__device__ __forceinline__ void cp_commit() {
    asm volatile("cp.async.commit_group;" ::: "memory");
}
__device__ __forceinline__ void cp_wait1() {
    asm volatile("cp.async.wait_group 1;" ::: "memory");
}

__device__ __forceinline__ void ldmx4(uint32_t* r, uint32_t addr) {
    asm volatile("ldmatrix.sync.aligned.m8n8.x4.shared.b16 {%0,%1,%2,%3}, [%4];"
                 : "=r"(r[0]), "=r"(r[1]), "=r"(r[2]), "=r"(r[3]) : "r"(addr));
}

__device__ __forceinline__ void mma_f16(float* d, const uint32_t* a,
                                        const uint32_t* b) {
    asm volatile(
        "mma.sync.aligned.m16n8k16.row.col.f32.f16.f16.f32 "
        "{%0,%1,%2,%3}, {%4,%5,%6,%7}, {%8,%9}, {%0,%1,%2,%3};"
        : "+f"(d[0]), "+f"(d[1]), "+f"(d[2]), "+f"(d[3])
        : "r"(a[0]), "r"(a[1]), "r"(a[2]), "r"(a[3]), "r"(b[0]), "r"(b[1]));
}

// SMEM swizzle for 64B rows (conflict-free ldmatrix)
__device__ __forceinline__ uint32_t sw_off(uint32_t r, uint32_t kb) {
    return r * 64 + (kb ^ (((r >> 1) & 3) << 4));
}

// ---------------------------------------------------------------------------
// Converts
// ---------------------------------------------------------------------------
__global__ void convert_h(const float* __restrict__ src,
                          __half* __restrict__ dst, int n4)
{
    for (int i = blockIdx.x * blockDim.x + threadIdx.x; i < n4;
         i += gridDim.x * blockDim.x) {
        float4 f = ((const float4*)src)[i];
        __half2 p0 = __floats2half2_rn(f.x, f.y);
        __half2 p1 = __floats2half2_rn(f.z, f.w);
        ((uint2*)dst)[i] = make_uint2(*(uint32_t*)&p0, *(uint32_t*)&p1);
    }
}

// Weights with row remapping: Wk row d -> 2d, Wv row d -> 2d+1 (interleaved),
// Wr -> 2048+d, Wo -> 3072+d. blockIdx.y selects the source matrix.
__global__ void convert_w4(const float* __restrict__ w0,
                           const float* __restrict__ w1,
                           const float* __restrict__ w2,
                           const float* __restrict__ w3,
                           __half* __restrict__ dst)
{
    const int n4 = DIM * DIM / 4;
    const int ROW4 = DIM / 4;
    const int m = blockIdx.y;
    const float* src = (m == 0) ? w0 : (m == 1) ? w1 : (m == 2) ? w2 : w3;
    for (int i = blockIdx.x * blockDim.x + threadIdx.x; i < n4;
         i += gridDim.x * blockDim.x) {
        const int srow = i / ROW4;
        const int c4 = i - srow * ROW4;
        int drow;
        if (m == 0)      drow = 2 * srow;          // Wk
        else if (m == 1) drow = 2 * srow + 1;      // Wv
        else if (m == 2) drow = 2048 + srow;       // Wr
        else             drow = 3072 + srow;       // Wo
        float4 f = ((const float4*)src)[i];
        __half2 p0 = __floats2half2_rn(f.x, f.y);
        __half2 p1 = __floats2half2_rn(f.z, f.w);
        ((uint2*)dst)[(size_t)drow * ROW4 + c4] =
            make_uint2(*(uint32_t*)&p0, *(uint32_t*)&p1);
    }
}

// ---------------------------------------------------------------------------
// fp16 NT GEMM via mma.sync. MODE 0: plain fp32 output (ldc = DIM).
// MODE 1: fused kvr epilogue — tiles with bn<2048 hold interleaved (k,v)
// column pairs: write kv product (fp16) to g_kvh; tiles with bn>=2048 write
// r (fp16) to g_rh. grid (N/BN, MROWS/BM), 256 threads, 3-stage pipeline.
// ---------------------------------------------------------------------------
template <int MODE>
__global__ __launch_bounds__(GTHREADS, 2)
void gemm_fp16(const __half* __restrict__ Ah,
               const __half* __restrict__ Bh,
               float* __restrict__ C)
{
    extern __shared__ char smem[];
    const uint32_t sb = smem_u32(smem);
    const int tid = threadIdx.x;
    const int wid = tid >> 5;
    const int lane = tid & 31;
    const int bm = blockIdx.y * BM;
    const int bn = blockIdx.x * BN;

    const int warp_m = (wid >> 1) * 32;   // 0,32,64,96
    const int warp_n = (wid & 1) * 64;    // 0,64

    auto issue_stage = [&](int c, int s) {
        const uint32_t stage = sb + s * STAGE_B;
#pragma unroll
        for (int tile = 0; tile < 2; tile++) {
            const __half* src = tile ? Bh : Ah;
            const int rowbase = tile ? bn : bm;
#pragma unroll
            for (int i = 0; i < 2; i++) {
                const int idx = i * 256 + tid;   // 0..511
                const uint32_t r = idx >> 2;
                const uint32_t kq = (idx & 3) * 16;
                const uint32_t dst = stage + tile * TILE_B + sw_off(r, kq);
                const char* sp = (const char*)(src + (size_t)(rowbase + r) * DIM
                                               + c * BK) + kq;
                cp_async16(dst, sp);
            }
        }
    };

    issue_stage(0, 0); cp_commit();
    issue_stage(1, 1); cp_commit();

    float acc[2][8][4];
#pragma unroll
    for (int mt = 0; mt < 2; mt++)
#pragma unroll
        for (int nt = 0; nt < 8; nt++)
#pragma unroll
            for (int j = 0; j < 4; j++) acc[mt][nt][j] = 0.0f;

    const int gA = lane >> 3, rlA = lane & 7;
    const int a_row_off = (gA & 1) * 8 + rlA;
    const int a_kb_off = (gA >> 1) * 16;
    const int b_row_off = (gA >> 1) * 8 + rlA;
    const int b_kb_off = (gA & 1) * 16;

    for (int c = 0; c < KCHUNKS; c++) {
        cp_wait1();
        __syncthreads();
        if (c + 2 < KCHUNKS) issue_stage(c + 2, (c + 2) % NSTAGE);
        cp_commit();

        const uint32_t stage = sb + (c % NSTAGE) * STAGE_B;
        const uint32_t sB = stage + TILE_B;

#pragma unroll
        for (int ks = 0; ks < 2; ks++) {
            const uint32_t kbase = ks * 32;
            uint32_t a[2][4];
#pragma unroll
            for (int mt = 0; mt < 2; mt++) {
                const uint32_t r = warp_m + mt * 16 + a_row_off;
                const uint32_t kb = kbase + a_kb_off;
                ldmx4(a[mt], stage + sw_off(r, kb));
            }
            uint32_t bh[8][2];
#pragma unroll
            for (int p = 0; p < 4; p++) {
                const uint32_t n = warp_n + p * 16 + b_row_off;
                const uint32_t kb = kbase + b_kb_off;
                uint32_t t4[4];
                ldmx4(t4, sB + sw_off(n, kb));
                bh[2 * p][0] = t4[0]; bh[2 * p][1] = t4[1];
                bh[2 * p + 1][0] = t4[2]; bh[2 * p + 1][1] = t4[3];
            }
#pragma unroll
            for (int mt = 0; mt < 2; mt++)
#pragma unroll
                for (int nt = 0; nt < 8; nt++)
                    mma_f16(acc[mt][nt], a[mt], bh[nt]);
        }
        __syncthreads();
    }

    const int er = lane >> 2;
    const int ec = (lane & 3) * 2;

    if (MODE == 0) {
#pragma unroll
        for (int mt = 0; mt < 2; mt++) {
            const int row0 = bm + warp_m + mt * 16 + er;
#pragma unroll
            for (int nt = 0; nt < 8; nt++) {
                const int col = bn + warp_n + nt * 8 + ec;
                *(float2*)(C + (size_t)row0 * DIM + col) =
                    make_float2(acc[mt][nt][0], acc[mt][nt][1]);
                *(float2*)(C + (size_t)(row0 + 8) * DIM + col) =
                    make_float2(acc[mt][nt][2], acc[mt][nt][3]);
            }
        }
    } else {
        if (bn < 2048) {
            // acc cols (col, col+1) = (k_d, v_d), d = col>>1. Write kv = k*v.
#pragma unroll
            for (int mt = 0; mt < 2; mt++) {
                const int row0 = bm + warp_m + mt * 16 + er;
#pragma unroll
                for (int nt = 0; nt < 8; nt++) {
                    const int col = bn + warp_n + nt * 8 + ec;
                    const int d = col >> 1;
                    g_kvh[(size_t)row0 * DIM + d] =
                        __float2half_rn(acc[mt][nt][0] * acc[mt][nt][1]);
                    g_kvh[(size_t)(row0 + 8) * DIM + d] =
                        __float2half_rn(acc[mt][nt][2] * acc[mt][nt][3]);
                }
            }
        } else {
#pragma unroll
            for (int mt = 0; mt < 2; mt++) {
                const int row0 = bm + warp_m + mt * 16 + er;
#pragma unroll
                for (int nt = 0; nt < 8; nt++) {
                    const int col = bn - 2048 + warp_n + nt * 8 + ec;
                    *(__half2*)(g_rh + (size_t)row0 * DIM + col) =
                        __floats2half2_rn(acc[mt][nt][0], acc[mt][nt][1]);
                    *(__half2*)(g_rh + (size_t)(row0 + 8) * DIM + col) =
                        __floats2half2_rn(acc[mt][nt][2], acc[mt][nt][3]);
                }
            }
        }
    }
}

// ---------------------------------------------------------------------------
// Scan pass A: 2 channels/thread (half2 kv), per-chunk local reduction.
// grid (NCHUNK, BATCH), block 512.
// ---------------------------------------------------------------------------
__global__ void scan_passA(const float* __restrict__ td)
{
    const int d0 = 2 * threadIdx.x;
    const int c = blockIdx.x;
    const int b = blockIdx.y;

    const float dec0 = expf(-expf(td[d0]));
    const float dec1 = expf(-expf(td[d0 + 1]));

    const size_t base = ((size_t)b * SEQ + (size_t)c * CHUNK_L) * DIM + d0;
    float s0 = 0.0f, s1 = 0.0f;
#pragma unroll 4
    for (int t = 0; t < CHUNK_L; t++) {
        float2 kv = __half22float2(*(const __half2*)(g_kvh + base + (size_t)t * DIM));
        s0 = fmaf(dec0, s0, kv.x);
        s1 = fmaf(dec1, s1, kv.y);
    }
    *(float2*)(g_chunk_sum + ((size_t)b * NCHUNK + c) * DIM + d0) =
        make_float2(s0, s1);
}

// ---------------------------------------------------------------------------
// Scan pass B: sequential carry across chunks. grid BATCH, block 512.
// ---------------------------------------------------------------------------
__global__ void scan_passB(const float* __restrict__ td)
{
    const int d0 = 2 * threadIdx.x;
    const int b = blockIdx.x;

    const float dL0 = expf(-(float)CHUNK_L * expf(td[d0]));
    const float dL1 = expf(-(float)CHUNK_L * expf(td[d0 + 1]));

    float c0 = 0.0f, c1 = 0.0f;
#pragma unroll
    for (int c = 0; c < NCHUNK; c++) {
        const size_t idx = ((size_t)b * NCHUNK + c) * DIM + d0;
        *(float2*)(g_state_in + idx) = make_float2(c0, c1);
        float2 s = *(const float2*)(g_chunk_sum + idx);
        c0 = fmaf(dL0, c0, s.x);
        c1 = fmaf(dL1, c1, s.y);
    }
}

// ---------------------------------------------------------------------------
// Scan pass C: replay with incoming state; writes fp16 sigmoid(r)*wkv.
// grid (NCHUNK, BATCH), block 512.
// ---------------------------------------------------------------------------
__global__ void scan_passC(const float* __restrict__ td,
                           const float* __restrict__ tf)
{
    const int d0 = 2 * threadIdx.x;
    const int c = blockIdx.x;
    const int b = blockIdx.y;

    const float dec0 = expf(-expf(td[d0]));
    const float dec1 = expf(-expf(td[d0 + 1]));
    const float eu0  = expf(tf[d0]);
    const float eu1  = expf(tf[d0 + 1]);

    float2 st = *(const float2*)(g_state_in + ((size_t)b * NCHUNK + c) * DIM + d0);

    const size_t rowbase = (size_t)b * SEQ + (size_t)c * CHUNK_L;
#pragma unroll 4
    for (int t = 0; t < CHUNK_L; t++) {
        const size_t off = (rowbase + t) * DIM + d0;
        float2 kv = __half22float2(*(const __half2*)(g_kvh + off));
        float2 r2 = __half22float2(*(const __half2*)(g_rh + off));
        float wkv0 = fmaf(eu0, kv.x, st.x);
        float wkv1 = fmaf(eu1, kv.y, st.y);
        st.x = fmaf(dec0, st.x, kv.x);
        st.y = fmaf(dec1, st.y, kv.y);
        float rs0 = 1.0f / (1.0f + expf(-r2.x));
        float rs1 = 1.0f / (1.0f + expf(-r2.y));
        *(__half2*)(g_ohi + off) = __floats2half2_rn(rs0 * wkv0, rs1 * wkv1);
    }
}

// ---------------------------------------------------------------------------
// Launch
// ---------------------------------------------------------------------------
extern "C" void kernel_launch(void* const* d_in, const int* in_sizes, int n_in,
                              void* d_out, int out_size)
{
    const float* x  = (const float*)d_in[0];
    const float* Wk = (const float*)d_in[1];
    const float* Wv = (const float*)d_in[2];
    const float* Wr = (const float*)d_in[3];
    const float* Wo = (const float*)d_in[4];
    const float* td = (const float*)d_in[5];
    const float* tf = (const float*)d_in[6];
    float* out = (float*)d_out;

    __half *xhi, *wh, *ohi;
    cudaGetSymbolAddress((void**)&xhi, g_xhi);
    cudaGetSymbolAddress((void**)&wh,  g_wh);
    cudaGetSymbolAddress((void**)&ohi, g_ohi);

    cudaFuncSetAttribute(gemm_fp16<0>,
                         cudaFuncAttributeMaxDynamicSharedMemorySize, SMEM_TOTAL);
    cudaFuncSetAttribute(gemm_fp16<1>,
                         cudaFuncAttributeMaxDynamicSharedMemorySize, SMEM_TOTAL);

    // Converts: x -> fp16; weights -> fp16 with kv interleave
    convert_h<<<2048, 256>>>(x, xhi, MROWS * DIM / 4);
    convert_w4<<<dim3(256, 4), 256>>>(Wk, Wv, Wr, Wo, wh);

    // Fused k|v|r projection with kv-product epilogue
    dim3 ggrid_kvr(NKVR / BN, MROWS / BM);   // (24, 128)
    gemm_fp16<1><<<ggrid_kvr, GTHREADS, SMEM_TOTAL>>>(xhi, wh, nullptr);

    // Chunked linear scan
    dim3 sgrid(NCHUNK, BATCH);
    scan_passA<<<sgrid, DIM / 2>>>(td);
    scan_passB<<<BATCH, DIM / 2>>>(td);
    scan_passC<<<sgrid, DIM / 2>>>(td, tf);

    // Output projection: fp32 output
    dim3 ggrid_o(DIM / BN, MROWS / BM);      // (8, 128)
    gemm_fp16<0><<<ggrid_o, GTHREADS, SMEM_TOTAL>>>(ohi,
        wh + 3 * (size_t)DIM * DIM, out);
}